// round 13
// baseline (speedup 1.0000x reference)
#include <cuda_runtime.h>
#include <cstdint>

#define KMAX 16
#define NPTS 32768
#define N1 2435

__device__ float4 g_pts[NPTS];
__device__ int    g_idx[N1 * KMAX];
__device__ float  g_phi[N1 * KMAX * 45];
__device__ float  g_t[N1 * 45 * 64];
__device__ float  g_xa[N1 * 64];
__device__ float  g_xb[N1 * 64];
__device__ float  g_f1[N1 * 64];
__device__ float  g_f2[181 * 128];
__device__ float  g_f3[13 * 256];
__device__ float  g_f4[512];
__device__ float  g_res[N1 * 64];

__device__ __forceinline__ bool lexless(float d1, int i1, float d2, int i2) {
    return (d1 < d2) || (d1 == d2 && i1 < i2);
}
#define F_INF __int_as_float(0x7f800000)

// ---------------------------------------------------------------------------
// LAPACK-faithful 3x3 symmetric eigendecomposition (ssyevd path, fp32)
// ---------------------------------------------------------------------------
__device__ __forceinline__ float slapy2(float x, float y) {
    float xa = fabsf(x), ya = fabsf(y);
    float w = fmaxf(xa, ya), z = fminf(xa, ya);
    if (z == 0.f) return w;
    float q = __fdiv_rn(z, w);
    return __fmul_rn(w, __fsqrt_rn(__fadd_rn(1.f, __fmul_rn(q, q))));
}

__device__ void slaev2(float a, float b, float c,
                       float* rt1, float* rt2, float* cs1, float* sn1) {
    float sm = __fadd_rn(a, c), df = __fsub_rn(a, c), adf = fabsf(df);
    float tb = __fadd_rn(b, b), ab = fabsf(tb);
    float acmx, acmn;
    if (fabsf(a) > fabsf(c)) { acmx = a; acmn = c; } else { acmx = c; acmn = a; }
    float rt;
    if (adf > ab) {
        float q = __fdiv_rn(ab, adf);
        rt = __fmul_rn(adf, __fsqrt_rn(__fadd_rn(1.f, __fmul_rn(q, q))));
    } else if (adf < ab) {
        float q = __fdiv_rn(adf, ab);
        rt = __fmul_rn(ab, __fsqrt_rn(__fadd_rn(1.f, __fmul_rn(q, q))));
    } else {
        rt = __fmul_rn(ab, __fsqrt_rn(2.f));
    }
    int sgn1;
    if (sm < 0.f) {
        *rt1 = __fmul_rn(0.5f, __fsub_rn(sm, rt)); sgn1 = -1;
        *rt2 = __fsub_rn(__fmul_rn(__fdiv_rn(acmx, *rt1), acmn),
                         __fmul_rn(__fdiv_rn(b, *rt1), b));
    } else if (sm > 0.f) {
        *rt1 = __fmul_rn(0.5f, __fadd_rn(sm, rt)); sgn1 = 1;
        *rt2 = __fsub_rn(__fmul_rn(__fdiv_rn(acmx, *rt1), acmn),
                         __fmul_rn(__fdiv_rn(b, *rt1), b));
    } else {
        *rt1 = __fmul_rn(0.5f, rt); *rt2 = __fmul_rn(-0.5f, rt); sgn1 = 1;
    }
    float cs; int sgn2;
    if (df >= 0.f) { cs = __fadd_rn(df, rt); sgn2 = 1; }
    else           { cs = __fsub_rn(df, rt); sgn2 = -1; }
    float acs = fabsf(cs);
    if (acs > ab) {
        float ct = __fdiv_rn(-tb, cs);
        *sn1 = __fdiv_rn(1.f, __fsqrt_rn(__fadd_rn(1.f, __fmul_rn(ct, ct))));
        *cs1 = __fmul_rn(ct, *sn1);
    } else {
        if (ab == 0.f) { *cs1 = 1.f; *sn1 = 0.f; }
        else {
            float tn = __fdiv_rn(-cs, tb);
            *cs1 = __fdiv_rn(1.f, __fsqrt_rn(__fadd_rn(1.f, __fmul_rn(tn, tn))));
            *sn1 = __fmul_rn(tn, *cs1);
        }
    }
    if (sgn1 == sgn2) { float tn = *cs1; *cs1 = -*sn1; *sn1 = tn; }
}

// LAPACK >=3.10 slartg (c >= 0 convention)
__device__ __forceinline__ void slartg(float f, float g, float* c, float* s, float* r) {
    if (g == 0.f) { *c = 1.f; *s = 0.f; *r = f; }
    else if (f == 0.f) { *c = 0.f; *s = (g > 0.f ? 1.f : -1.f); *r = fabsf(g); }
    else {
        float d = __fsqrt_rn(__fadd_rn(__fmul_rn(f, f), __fmul_rn(g, g)));
        *c = __fdiv_rn(fabsf(f), d);
        *r = (f > 0.f ? d : -d);
        *s = __fdiv_rn(g, *r);
    }
}

__device__ void ssteqr3(float d[3], float e[2], float Z[3][3]) {
    const float eps = 5.9604645e-8f;           // SLAMCH('E') fp32
    const float eps2 = eps * eps;
    const float safmin = 1.17549435e-38f;
    const int n = 3, nmaxit = 90;
    int jtot = 0, l1 = 0;
    while (l1 < n) {
        if (l1 > 0) e[l1 - 1] = 0.f;
        int m;
        for (m = l1; m < n - 1; m++) {
            float tst = fabsf(e[m]);
            if (tst == 0.f) break;
            if (tst <= __fmul_rn(__fmul_rn(__fsqrt_rn(fabsf(d[m])),
                                           __fsqrt_rn(fabsf(d[m + 1]))), eps)) {
                e[m] = 0.f; break;
            }
        }
        int l = l1, lend = m;
        l1 = m + 1;
        if (lend == l) continue;
        if (fabsf(d[lend]) < fabsf(d[l])) { int t = l; l = lend; lend = t; }
        if (lend > l) {
            // QL iteration
            for (;;) {
                int mm = lend;
                for (int i = l; i < lend; i++) {
                    float tst = __fmul_rn(e[i], e[i]);
                    if (tst <= __fadd_rn(__fmul_rn(__fmul_rn(eps2, fabsf(d[i])),
                                                   fabsf(d[i + 1])), safmin)) { mm = i; break; }
                }
                if (mm < lend) e[mm] = 0.f;
                float p = d[l];
                if (mm == l) { d[l] = p; l++; if (l <= lend) continue; break; }
                if (mm == l + 1) {
                    float rt1, rt2, c, s;
                    slaev2(d[l], e[l], d[l + 1], &rt1, &rt2, &c, &s);
                    for (int k = 0; k < 3; k++) {
                        float tmp = Z[k][l + 1];
                        Z[k][l + 1] = __fsub_rn(__fmul_rn(c, tmp), __fmul_rn(s, Z[k][l]));
                        Z[k][l]     = __fadd_rn(__fmul_rn(s, tmp), __fmul_rn(c, Z[k][l]));
                    }
                    d[l] = rt1; d[l + 1] = rt2; e[l] = 0.f;
                    l += 2; if (l <= lend) continue; break;
                }
                if (jtot == nmaxit) break;
                jtot++;
                float g = __fdiv_rn(__fsub_rn(d[l + 1], p), __fmul_rn(2.f, e[l]));
                float r = slapy2(g, 1.f);
                g = __fadd_rn(__fsub_rn(d[mm], p),
                              __fdiv_rn(e[l], __fadd_rn(g, copysignf(r, g))));
                float s = 1.f, c = 1.f;
                p = 0.f;
                float csv[2], snv[2];
                for (int i = mm - 1; i >= l; i--) {
                    float f = __fmul_rn(s, e[i]), b = __fmul_rn(c, e[i]);
                    slartg(g, f, &c, &s, &r);
                    if (i != mm - 1) e[i + 1] = r;
                    g = __fsub_rn(d[i + 1], p);
                    r = __fadd_rn(__fmul_rn(__fsub_rn(d[i], g), s),
                                  __fmul_rn(__fmul_rn(2.f, c), b));
                    p = __fmul_rn(s, r);
                    d[i + 1] = __fadd_rn(g, p);
                    g = __fsub_rn(__fmul_rn(c, r), b);
                    csv[i] = c; snv[i] = -s;
                }
                for (int j = mm - 1; j >= l; j--) {
                    float C = csv[j], S = snv[j];
                    for (int k = 0; k < 3; k++) {
                        float tmp = Z[k][j + 1];
                        Z[k][j + 1] = __fsub_rn(__fmul_rn(C, tmp), __fmul_rn(S, Z[k][j]));
                        Z[k][j]     = __fadd_rn(__fmul_rn(S, tmp), __fmul_rn(C, Z[k][j]));
                    }
                }
                d[l] = __fsub_rn(d[l], p); e[l] = g;
            }
        } else {
            // QR iteration
            for (;;) {
                int mm = lend;
                for (int i = l; i > lend; i--) {
                    float tst = __fmul_rn(e[i - 1], e[i - 1]);
                    if (tst <= __fadd_rn(__fmul_rn(__fmul_rn(eps2, fabsf(d[i])),
                                                   fabsf(d[i - 1])), safmin)) { mm = i; break; }
                }
                if (mm > lend) e[mm - 1] = 0.f;
                float p = d[l];
                if (mm == l) { d[l] = p; l--; if (l >= lend) continue; break; }
                if (mm == l - 1) {
                    float rt1, rt2, c, s;
                    slaev2(d[l - 1], e[l - 1], d[l], &rt1, &rt2, &c, &s);
                    for (int k = 0; k < 3; k++) {
                        float tmp = Z[k][l];
                        Z[k][l]     = __fsub_rn(__fmul_rn(c, tmp), __fmul_rn(s, Z[k][l - 1]));
                        Z[k][l - 1] = __fadd_rn(__fmul_rn(s, tmp), __fmul_rn(c, Z[k][l - 1]));
                    }
                    d[l - 1] = rt1; d[l] = rt2; e[l - 1] = 0.f;
                    l -= 2; if (l >= lend) continue; break;
                }
                if (jtot == nmaxit) break;
                jtot++;
                float g = __fdiv_rn(__fsub_rn(d[l - 1], p), __fmul_rn(2.f, e[l - 1]));
                float r = slapy2(g, 1.f);
                g = __fadd_rn(__fsub_rn(d[mm], p),
                              __fdiv_rn(e[l - 1], __fadd_rn(g, copysignf(r, g))));
                float s = 1.f, c = 1.f;
                p = 0.f;
                float csv[2], snv[2];
                for (int i = mm; i <= l - 1; i++) {
                    float f = __fmul_rn(s, e[i]), b = __fmul_rn(c, e[i]);
                    slartg(g, f, &c, &s, &r);
                    if (i != mm) e[i - 1] = r;
                    g = __fsub_rn(d[i], p);
                    r = __fadd_rn(__fmul_rn(__fsub_rn(d[i + 1], g), s),
                                  __fmul_rn(__fmul_rn(2.f, c), b));
                    p = __fmul_rn(s, r);
                    d[i] = __fadd_rn(g, p);
                    g = __fsub_rn(__fmul_rn(c, r), b);
                    csv[i] = c; snv[i] = s;
                }
                for (int j = mm; j <= l - 1; j++) {
                    float C = csv[j], S = snv[j];
                    for (int k = 0; k < 3; k++) {
                        float tmp = Z[k][j + 1];
                        Z[k][j + 1] = __fsub_rn(__fmul_rn(C, tmp), __fmul_rn(S, Z[k][j]));
                        Z[k][j]     = __fadd_rn(__fmul_rn(S, tmp), __fmul_rn(C, Z[k][j]));
                    }
                }
                d[l] = __fsub_rn(d[l], p); e[l - 1] = g;
            }
        }
    }
    // ascending selection sort (LAPACK ssteqr final sort), swap columns
    for (int ii = 1; ii < n; ii++) {
        int i = ii - 1, k = i;
        float p = d[i];
        for (int j = ii; j < n; j++) if (d[j] < p) { k = j; p = d[j]; }
        if (k != i) {
            d[k] = d[i]; d[i] = p;
            for (int r2 = 0; r2 < 3; r2++) {
                float t = Z[r2][i]; Z[r2][i] = Z[r2][k]; Z[r2][k] = t;
            }
        }
    }
}

// full ssyevd path for 3x3 (lower triangle input), V columns = eigenvectors asc.
__device__ void eigh3(float a00, float a10, float a11, float a20, float a21, float a22,
                      float V[3][3]) {
    float d[3], e[2], tau, v2;
    d[0] = a00;
    float xnorm = fabsf(a20);
    if (xnorm == 0.f) {
        tau = 0.f; v2 = 0.f;
        e[0] = a10; d[1] = a11; d[2] = a22; e[1] = a21;
    } else {
        float alpha = a10;
        float beta = -copysignf(slapy2(alpha, xnorm), alpha);
        tau = __fdiv_rn(__fsub_rn(beta, alpha), beta);
        v2 = __fmul_rn(a20, __fdiv_rn(1.f, __fsub_rn(alpha, beta)));
        e[0] = beta;
        float w0 = __fmul_rn(tau, __fadd_rn(a11, __fmul_rn(a21, v2)));
        float w1 = __fmul_rn(tau, __fadd_rn(a21, __fmul_rn(a22, v2)));
        float al = __fmul_rn(__fmul_rn(-0.5f, tau), __fadd_rn(w0, __fmul_rn(w1, v2)));
        w0 = __fadd_rn(w0, al);
        w1 = __fadd_rn(w1, __fmul_rn(al, v2));
        d[1] = __fsub_rn(a11, __fmul_rn(2.f, w0));
        e[1] = __fsub_rn(a21, __fadd_rn(__fmul_rn(v2, w0), w1));
        d[2] = __fsub_rn(a22, __fmul_rn(2.f, __fmul_rn(v2, w1)));
    }
    float Z[3][3] = {{1.f,0.f,0.f},{0.f,1.f,0.f},{0.f,0.f,1.f}};
    ssteqr3(d, e, Z);
    // sormtr: V = H1 * Z, H1 = I - tau*v*v^T, v = (0,1,v2)
    if (tau != 0.f) {
        for (int c = 0; c < 3; c++) {
            float dot = __fadd_rn(Z[1][c], __fmul_rn(v2, Z[2][c]));
            float td = __fmul_rn(tau, dot);
            Z[1][c] = __fsub_rn(Z[1][c], td);
            Z[2][c] = __fsub_rn(Z[2][c], __fmul_rn(td, v2));
        }
    }
    for (int r = 0; r < 3; r++)
        for (int c = 0; c < 3; c++) V[r][c] = Z[r][c];
}

// ---------------------------------------------------------------------------
__global__ void k_prep(const float* __restrict__ pos, int n) {
    int i = blockIdx.x * blockDim.x + threadIdx.x;
    if (i < n) {
        float x = pos[3*i], y = pos[3*i+1], z = pos[3*i+2];
        float ss = __fadd_rn(__fadd_rn(__fmul_rn(x,x), __fmul_rn(y,y)), __fmul_rn(z,z));
        g_pts[i] = make_float4(x, y, z, ss);
    }
}

// one query per warp; smem-staged source tiles; per-lane sorted top-16; warp merge
__global__ __launch_bounds__(256) void k_knn(int Q, int S, int K) {
    __shared__ __align__(16) char sbuf[32768];
    float4* stage = (float4*)sbuf;
    float*  sd = (float*)sbuf;
    int*    si = (int*)(sbuf + 16384);
    int w = threadIdx.x >> 5, lane = threadIdx.x & 31;
    int q = blockIdx.x * 8 + w;
    bool act = (q < Q);
    float qx=0,qy=0,qz=0,qq=0;
    if (act) { float4 p = g_pts[q]; qx=p.x; qy=p.y; qz=p.z; qq=p.w; }
    float bd[KMAX]; int bi[KMAX];
#pragma unroll
    for (int j = 0; j < KMAX; j++) { bd[j]=F_INF; bi[j]=0x7FFFFFFF; }
    for (int t0 = 0; t0 < S; t0 += 1024) {
        int cnt = min(1024, S - t0);
        __syncthreads();
        for (int i = threadIdx.x; i < cnt; i += 256) stage[i] = g_pts[t0 + i];
        __syncthreads();
        if (act) for (int i = lane; i < cnt; i += 32) {
            float4 p = stage[i]; int s = t0 + i;
            float G = __fadd_rn(__fadd_rn(__fmul_rn(qx,p.x), __fmul_rn(qy,p.y)), __fmul_rn(qz,p.z));
            float d = __fsub_rn(__fadd_rn(qq, p.w), __fmul_rn(2.0f, G));
            if (lexless(d, s, bd[KMAX-1], bi[KMAX-1])) {
                float cd = d; int ci = s;
#pragma unroll
                for (int j = 0; j < KMAX; j++)
                    if (lexless(cd, ci, bd[j], bi[j])) {
                        float td=bd[j]; int ti=bi[j]; bd[j]=cd; bi[j]=ci; cd=td; ci=ti;
                    }
            }
        }
    }
    __syncthreads();
    if (!act) return;
    float* swd = sd + w * 512; int* swi = si + w * 512;
#pragma unroll
    for (int j = 0; j < KMAX; j++) { swd[lane*KMAX+j]=bd[j]; swi[lane*KMAX+j]=bi[j]; }
    __syncwarp();
    int ptr = 0;
    for (int r = 0; r < K; r++) {
        float d = swd[lane*KMAX+ptr]; int i = swi[lane*KMAX+ptr]; int ln = lane;
#pragma unroll
        for (int off = 16; off > 0; off >>= 1) {
            float d2 = __shfl_xor_sync(0xffffffff, d, off);
            int   i2 = __shfl_xor_sync(0xffffffff, i, off);
            int   l2 = __shfl_xor_sync(0xffffffff, ln, off);
            if (lexless(d2, i2, d, i)) { d=d2; i=i2; ln=l2; }
        }
        if (lane == ln) { g_idx[q*KMAX+r] = i; ptr++; }
        __syncwarp();
    }
}

__global__ __launch_bounds__(256) void k_geom(int Q, int K, const float* __restrict__ pos) {
    int w = threadIdx.x >> 5, lane = threadIdx.x & 31;
    int q = blockIdx.x * 8 + w;
    if (q >= Q) return;
    float qx = pos[3*q], qy = pos[3*q+1], qz = pos[3*q+2];
    float rx=0, ry=0, rz=0, nrm=0;
    if (lane < K) {
        int s = g_idx[q*KMAX+lane];
        rx = __fsub_rn(pos[3*s],   qx);
        ry = __fsub_rn(pos[3*s+1], qy);
        rz = __fsub_rn(pos[3*s+2], qz);
        nrm = __fsqrt_rn(__fadd_rn(__fadd_rn(__fmul_rn(rx,rx),__fmul_rn(ry,ry)),__fmul_rn(rz,rz)));
    }
    float mx = nrm;
#pragma unroll
    for (int off = 16; off > 0; off >>= 1) mx = fmaxf(mx, __shfl_xor_sync(0xffffffff, mx, off));
    float den = __fadd_rn(mx, 1e-8f);
    if (lane < K) { rx=__fdiv_rn(rx,den); ry=__fdiv_rn(ry,den); rz=__fdiv_rn(rz,den); }
    else { rx=ry=rz=0.f; }
    // covariance (fp32, warp tree reduction)
    float c00=__fmul_rn(rx,rx), c01=__fmul_rn(rx,ry), c02=__fmul_rn(rx,rz);
    float c11=__fmul_rn(ry,ry), c12=__fmul_rn(ry,rz), c22=__fmul_rn(rz,rz);
#pragma unroll
    for (int off = 16; off > 0; off >>= 1) {
        c00=__fadd_rn(c00,__shfl_xor_sync(0xffffffff,c00,off));
        c01=__fadd_rn(c01,__shfl_xor_sync(0xffffffff,c01,off));
        c02=__fadd_rn(c02,__shfl_xor_sync(0xffffffff,c02,off));
        c11=__fadd_rn(c11,__shfl_xor_sync(0xffffffff,c11,off));
        c12=__fadd_rn(c12,__shfl_xor_sync(0xffffffff,c12,off));
        c22=__fadd_rn(c22,__shfl_xor_sync(0xffffffff,c22,off));
    }
    float fk=(float)K;
    float a00=__fdiv_rn(c00,fk), a01=__fdiv_rn(c01,fk), a02=__fdiv_rn(c02,fk);
    float a11=__fdiv_rn(c11,fk), a12=__fdiv_rn(c12,fk), a22=__fdiv_rn(c22,fk);

    float V[3][3];
    eigh3(a00, a01, a11, a02, a12, a22, V);   // lower: a10=a01, a20=a02, a21=a12

    if (lane < K) {
        float X=__fmaf_rn(rz,V[2][0],__fmaf_rn(ry,V[1][0],__fmul_rn(rx,V[0][0])));
        float Y=__fmaf_rn(rz,V[2][1],__fmaf_rn(ry,V[1][1],__fmul_rn(rx,V[0][1])));
        float Z=__fmaf_rn(rz,V[2][2],__fmaf_rn(ry,V[1][2],__fmul_rn(rx,V[0][2])));
        float px[5], py[3], pz[3];
        px[0]=1.f; px[1]=X; px[2]=__fmul_rn(X,X); px[3]=__fmul_rn(px[2],X); px[4]=__fmul_rn(px[3],X);
        py[0]=1.f; py[1]=Y; py[2]=__fmul_rn(Y,Y);
        pz[0]=1.f; pz[1]=Z; pz[2]=__fmul_rn(Z,Z);
        float* dst = g_phi + (q*KMAX+lane)*45;
#pragma unroll
        for (int n = 0; n < 5; n++)
#pragma unroll
            for (int l = 0; l < 3; l++)
#pragma unroll
                for (int m = 0; m < 3; m++)
                    dst[n*9+l*3+m] = __fmul_rn(__fmul_rn(px[n],py[l]),pz[m]);
    }
}

// t[q] = (phi^T nf)/k
__global__ __launch_bounds__(128) void k_tker(int K, int C, const float* __restrict__ nf,
                                              float* __restrict__ tout) {
    __shared__ int   sidx[KMAX];
    __shared__ float sphi[KMAX*45];
    __shared__ float snf[KMAX*256];
    int q = blockIdx.x, tid = threadIdx.x;
    if (tid < K) sidx[tid] = g_idx[q*KMAX+tid];
    for (int e = tid; e < K*45; e += 128) sphi[e] = g_phi[q*KMAX*45 + e];
    __syncthreads();
    for (int kk = 0; kk < K; kk++) {
        int row = sidx[kk];
        for (int c = tid; c < C; c += 128) snf[kk*C+c] = nf[row*C+c];
    }
    __syncthreads();
    int E = 45*C; float fk = (float)K;
    for (int e = tid; e < E; e += 128) {
        int b = e / C, c = e - b*C;
        float acc = 0.f;
        for (int kk = 0; kk < K; kk++)
            acc = __fmaf_rn(sphi[kk*45+b], snf[kk*C+c], acc);
        tout[q*E+e] = __fdiv_rn(acc, fk);
    }
}

// out[M,N] = X[M,K]@W[K,N] (+bias)(relu); N % 64 == 0
__global__ __launch_bounds__(128) void k_gemm(int M, int N, int K,
                                              const float* __restrict__ X,
                                              const float* __restrict__ W,
                                              const float* __restrict__ bias,
                                              float* __restrict__ out, int relu) {
    __shared__ float Xs[16][33];
    __shared__ __align__(16) float Ws[32][64];
    int m0 = blockIdx.x*16, n0 = blockIdx.y*64;
    int tid = threadIdx.x, tn = tid & 15, tm = tid >> 4;
    float acc[2][4] = {};
    for (int k0 = 0; k0 < K; k0 += 32) {
#pragma unroll
        for (int j = 0; j < 4; j++) {
            int id = tid*4+j, r = id>>5, c = id&31;
            float v = 0.f;
            if (m0+r < M && k0+c < K) v = X[(m0+r)*K + k0+c];
            Xs[r][c] = v;
        }
#pragma unroll
        for (int j = 0; j < 16; j++) {
            int id = tid + j*128, r = id>>6, c = id&63;
            float v = 0.f;
            if (k0+r < K) v = W[(k0+r)*N + n0+c];
            Ws[r][c] = v;
        }
        __syncthreads();
#pragma unroll
        for (int kk = 0; kk < 32; kk++) {
            float a0 = Xs[tm*2][kk], a1 = Xs[tm*2+1][kk];
            float4 b = *(const float4*)&Ws[kk][tn*4];
            acc[0][0]=__fmaf_rn(a0,b.x,acc[0][0]); acc[0][1]=__fmaf_rn(a0,b.y,acc[0][1]);
            acc[0][2]=__fmaf_rn(a0,b.z,acc[0][2]); acc[0][3]=__fmaf_rn(a0,b.w,acc[0][3]);
            acc[1][0]=__fmaf_rn(a1,b.x,acc[1][0]); acc[1][1]=__fmaf_rn(a1,b.y,acc[1][1]);
            acc[1][2]=__fmaf_rn(a1,b.z,acc[1][2]); acc[1][3]=__fmaf_rn(a1,b.w,acc[1][3]);
        }
        __syncthreads();
    }
#pragma unroll
    for (int i = 0; i < 2; i++) {
        int m = m0 + tm*2 + i;
        if (m < M)
#pragma unroll
            for (int j = 0; j < 4; j++) {
                int n = n0 + tn*4 + j;
                float y = acc[i][j];
                if (bias) y = __fadd_rn(y, bias[n]);
                if (relu) y = fmaxf(y, 0.f);
                out[m*N+n] = y;
            }
    }
}

__global__ void k_addrelu(int n, const float* __restrict__ x,
                          const float* __restrict__ r, float* __restrict__ o) {
    int i = blockIdx.x*256 + threadIdx.x;
    if (i < n) o[i] = fmaxf(__fadd_rn(x[i], r[i]), 0.f);
}

__global__ __launch_bounds__(128) void k_head(const float* __restrict__ hw,
                                              const float* __restrict__ hb,
                                              float* __restrict__ out) {
    __shared__ float red[128];
    int tid = threadIdx.x;
    float acc = 0.f;
    for (int i = tid; i < 512; i += 128)
        acc = __fmaf_rn(g_f4[i], hw[i], acc);
    red[tid] = acc;
    __syncthreads();
    for (int s = 64; s > 0; s >>= 1) {
        if (tid < s) red[tid] = __fadd_rn(red[tid], red[tid+s]);
        __syncthreads();
    }
    if (tid == 0) out[0] = __fadd_rn(red[0], hb[0]);
}

extern "C" void kernel_launch(void* const* d_in, const int* in_sizes, int n_in,
                              void* d_out, int out_size) {
    const float* pos  = (const float*)d_in[0];
    const float* chan = (const float*)d_in[1];
    const float* w[7]; const float* b[7];
    for (int li = 0; li < 7; li++) { w[li] = (const float*)d_in[2+2*li]; b[li] = (const float*)d_in[3+2*li]; }
    const float* p1 = (const float*)d_in[16];
    const float* p2 = (const float*)d_in[17];
    const float* p3 = (const float*)d_in[18];
    const float* p4 = (const float*)d_in[19];
    const float* hw = (const float*)d_in[20];
    const float* hb = (const float*)d_in[21];
    float* out = (float*)d_out;

    void* pv;
    cudaGetSymbolAddress(&pv, g_t);   float* tp  = (float*)pv;
    cudaGetSymbolAddress(&pv, g_xa);  float* xa  = (float*)pv;
    cudaGetSymbolAddress(&pv, g_xb);  float* xb  = (float*)pv;
    cudaGetSymbolAddress(&pv, g_f1);  float* f1  = (float*)pv;
    cudaGetSymbolAddress(&pv, g_f2);  float* f2  = (float*)pv;
    cudaGetSymbolAddress(&pv, g_f3);  float* f3  = (float*)pv;
    cudaGetSymbolAddress(&pv, g_f4);  float* f4  = (float*)pv;
    cudaGetSymbolAddress(&pv, g_res); float* rs  = (float*)pv;

    k_prep<<<(NPTS+255)/256, 256>>>(pos, NPTS);

    // L1: Q=2435 S=32768 k=16 Cin=4 -> 64
    k_knn<<<(2435+7)/8, 256>>>(2435, NPTS, 16);
    k_geom<<<(2435+7)/8, 256>>>(2435, 16, pos);
    k_tker<<<2435, 128>>>(16, 4, chan, tp);
    k_gemm<<<dim3((2435+15)/16, 1), 128>>>(2435, 64, 180, tp, w[0], b[0], xa, 1);

    // L2: Q=2435 S=2435 k=16 Cin=64 -> 64
    k_knn<<<(2435+7)/8, 256>>>(2435, 2435, 16);
    k_geom<<<(2435+7)/8, 256>>>(2435, 16, pos);
    k_tker<<<2435, 128>>>(16, 64, xa, tp);
    k_gemm<<<dim3((2435+15)/16, 1), 128>>>(2435, 64, 2880, tp, w[1], b[1], xb, 1);
    k_gemm<<<dim3((2435+15)/16, 1), 128>>>(2435, 64, 4, chan, p1, nullptr, rs, 0);
    k_addrelu<<<(2435*64+255)/256, 256>>>(2435*64, xb, rs, f1);

    // L3: Q=181 S=2435 k=16 Cin=64 -> 128
    k_knn<<<(181+7)/8, 256>>>(181, 2435, 16);
    k_geom<<<(181+7)/8, 256>>>(181, 16, pos);
    k_tker<<<181, 128>>>(16, 64, f1, tp);
    k_gemm<<<dim3((181+15)/16, 2), 128>>>(181, 128, 2880, tp, w[2], b[2], xa, 1);

    // L4: Q=181 S=181 k=16 Cin=128 -> 128
    k_knn<<<(181+7)/8, 256>>>(181, 181, 16);
    k_geom<<<(181+7)/8, 256>>>(181, 16, pos);
    k_tker<<<181, 128>>>(16, 128, xa, tp);
    k_gemm<<<dim3((181+15)/16, 2), 128>>>(181, 128, 5760, tp, w[3], b[3], xb, 1);
    k_gemm<<<dim3((181+15)/16, 2), 128>>>(181, 128, 64, f1, p2, nullptr, rs, 0);
    k_addrelu<<<(181*128+255)/256, 256>>>(181*128, xb, rs, f2);

    // L5: Q=13 S=181 k=16 Cin=128 -> 256
    k_knn<<<2, 256>>>(13, 181, 16);
    k_geom<<<2, 256>>>(13, 16, pos);
    k_tker<<<13, 128>>>(16, 128, f2, tp);
    k_gemm<<<dim3(1, 4), 128>>>(13, 256, 5760, tp, w[4], b[4], xa, 1);

    // L6: Q=13 S=13 k=13 Cin=256 -> 256
    k_knn<<<2, 256>>>(13, 13, 13);
    k_geom<<<2, 256>>>(13, 13, pos);
    k_tker<<<13, 128>>>(13, 256, xa, tp);
    k_gemm<<<dim3(1, 4), 128>>>(13, 256, 11520, tp, w[5], b[5], xb, 1);
    k_gemm<<<dim3(1, 4), 128>>>(13, 256, 128, f2, p3, nullptr, rs, 0);
    k_addrelu<<<(13*256+255)/256, 256>>>(13*256, xb, rs, f3);

    // L7: Q=1 S=13 k=13 Cin=256 -> 512
    k_knn<<<1, 256>>>(1, 13, 13);
    k_geom<<<1, 256>>>(1, 13, pos);
    k_tker<<<1, 128>>>(13, 256, f3, tp);
    k_gemm<<<dim3(1, 8), 128>>>(1, 512, 11520, tp, w[6], b[6], xa, 1);
    k_gemm<<<dim3(1, 8), 128>>>(1, 512, 256, f3, p4, nullptr, rs, 0);
    k_addrelu<<<2, 256>>>(512, xa, rs, f4);

    k_head<<<1, 128>>>(hw, hb, out);
}

// round 14
// speedup vs baseline: 1.8905x; 1.8905x over previous
#include <cuda_runtime.h>
#include <cstdint>

#define KMAX 16
#define NPTS 32768
#define N1 2435

__device__ float4 g_pts[NPTS];
__device__ int    g_idx[N1 * KMAX];
__device__ float  g_cov[N1 * 6];
__device__ float  g_V[N1 * 9];
__device__ float  g_phi[N1 * KMAX * 45];
__device__ float  g_t[N1 * 45 * 64];
__device__ float  g_xa[N1 * 64];
__device__ float  g_xb[N1 * 64];
__device__ float  g_f1[N1 * 64];
__device__ float  g_f2[181 * 128];
__device__ float  g_f3[13 * 256];
__device__ float  g_f4[512];
__device__ float  g_part[4 * N1 * 64];   // split-K partials (max 623,360 floats)

__device__ __forceinline__ bool lexless(float d1, int i1, float d2, int i2) {
    return (d1 < d2) || (d1 == d2 && i1 < i2);
}
#define F_INF __int_as_float(0x7f800000)

// ---------------------------------------------------------------------------
// LAPACK-faithful 3x3 symmetric eigendecomposition (ssyevd path, fp32)
// (verified in R13 — do not modify)
// ---------------------------------------------------------------------------
__device__ __forceinline__ float slapy2(float x, float y) {
    float xa = fabsf(x), ya = fabsf(y);
    float w = fmaxf(xa, ya), z = fminf(xa, ya);
    if (z == 0.f) return w;
    float q = __fdiv_rn(z, w);
    return __fmul_rn(w, __fsqrt_rn(__fadd_rn(1.f, __fmul_rn(q, q))));
}

__device__ void slaev2(float a, float b, float c,
                       float* rt1, float* rt2, float* cs1, float* sn1) {
    float sm = __fadd_rn(a, c), df = __fsub_rn(a, c), adf = fabsf(df);
    float tb = __fadd_rn(b, b), ab = fabsf(tb);
    float acmx, acmn;
    if (fabsf(a) > fabsf(c)) { acmx = a; acmn = c; } else { acmx = c; acmn = a; }
    float rt;
    if (adf > ab) {
        float q = __fdiv_rn(ab, adf);
        rt = __fmul_rn(adf, __fsqrt_rn(__fadd_rn(1.f, __fmul_rn(q, q))));
    } else if (adf < ab) {
        float q = __fdiv_rn(adf, ab);
        rt = __fmul_rn(ab, __fsqrt_rn(__fadd_rn(1.f, __fmul_rn(q, q))));
    } else {
        rt = __fmul_rn(ab, __fsqrt_rn(2.f));
    }
    int sgn1;
    if (sm < 0.f) {
        *rt1 = __fmul_rn(0.5f, __fsub_rn(sm, rt)); sgn1 = -1;
        *rt2 = __fsub_rn(__fmul_rn(__fdiv_rn(acmx, *rt1), acmn),
                         __fmul_rn(__fdiv_rn(b, *rt1), b));
    } else if (sm > 0.f) {
        *rt1 = __fmul_rn(0.5f, __fadd_rn(sm, rt)); sgn1 = 1;
        *rt2 = __fsub_rn(__fmul_rn(__fdiv_rn(acmx, *rt1), acmn),
                         __fmul_rn(__fdiv_rn(b, *rt1), b));
    } else {
        *rt1 = __fmul_rn(0.5f, rt); *rt2 = __fmul_rn(-0.5f, rt); sgn1 = 1;
    }
    float cs; int sgn2;
    if (df >= 0.f) { cs = __fadd_rn(df, rt); sgn2 = 1; }
    else           { cs = __fsub_rn(df, rt); sgn2 = -1; }
    float acs = fabsf(cs);
    if (acs > ab) {
        float ct = __fdiv_rn(-tb, cs);
        *sn1 = __fdiv_rn(1.f, __fsqrt_rn(__fadd_rn(1.f, __fmul_rn(ct, ct))));
        *cs1 = __fmul_rn(ct, *sn1);
    } else {
        if (ab == 0.f) { *cs1 = 1.f; *sn1 = 0.f; }
        else {
            float tn = __fdiv_rn(-cs, tb);
            *cs1 = __fdiv_rn(1.f, __fsqrt_rn(__fadd_rn(1.f, __fmul_rn(tn, tn))));
            *sn1 = __fmul_rn(tn, *cs1);
        }
    }
    if (sgn1 == sgn2) { float tn = *cs1; *cs1 = -*sn1; *sn1 = tn; }
}

__device__ __forceinline__ void slartg(float f, float g, float* c, float* s, float* r) {
    if (g == 0.f) { *c = 1.f; *s = 0.f; *r = f; }
    else if (f == 0.f) { *c = 0.f; *s = (g > 0.f ? 1.f : -1.f); *r = fabsf(g); }
    else {
        float d = __fsqrt_rn(__fadd_rn(__fmul_rn(f, f), __fmul_rn(g, g)));
        *c = __fdiv_rn(fabsf(f), d);
        *r = (f > 0.f ? d : -d);
        *s = __fdiv_rn(g, *r);
    }
}

__device__ void ssteqr3(float d[3], float e[2], float Z[3][3]) {
    const float eps = 5.9604645e-8f;
    const float eps2 = eps * eps;
    const float safmin = 1.17549435e-38f;
    const int n = 3, nmaxit = 90;
    int jtot = 0, l1 = 0;
    while (l1 < n) {
        if (l1 > 0) e[l1 - 1] = 0.f;
        int m;
        for (m = l1; m < n - 1; m++) {
            float tst = fabsf(e[m]);
            if (tst == 0.f) break;
            if (tst <= __fmul_rn(__fmul_rn(__fsqrt_rn(fabsf(d[m])),
                                           __fsqrt_rn(fabsf(d[m + 1]))), eps)) {
                e[m] = 0.f; break;
            }
        }
        int l = l1, lend = m;
        l1 = m + 1;
        if (lend == l) continue;
        if (fabsf(d[lend]) < fabsf(d[l])) { int t = l; l = lend; lend = t; }
        if (lend > l) {
            for (;;) {
                int mm = lend;
                for (int i = l; i < lend; i++) {
                    float tst = __fmul_rn(e[i], e[i]);
                    if (tst <= __fadd_rn(__fmul_rn(__fmul_rn(eps2, fabsf(d[i])),
                                                   fabsf(d[i + 1])), safmin)) { mm = i; break; }
                }
                if (mm < lend) e[mm] = 0.f;
                float p = d[l];
                if (mm == l) { d[l] = p; l++; if (l <= lend) continue; break; }
                if (mm == l + 1) {
                    float rt1, rt2, c, s;
                    slaev2(d[l], e[l], d[l + 1], &rt1, &rt2, &c, &s);
                    for (int k = 0; k < 3; k++) {
                        float tmp = Z[k][l + 1];
                        Z[k][l + 1] = __fsub_rn(__fmul_rn(c, tmp), __fmul_rn(s, Z[k][l]));
                        Z[k][l]     = __fadd_rn(__fmul_rn(s, tmp), __fmul_rn(c, Z[k][l]));
                    }
                    d[l] = rt1; d[l + 1] = rt2; e[l] = 0.f;
                    l += 2; if (l <= lend) continue; break;
                }
                if (jtot == nmaxit) break;
                jtot++;
                float g = __fdiv_rn(__fsub_rn(d[l + 1], p), __fmul_rn(2.f, e[l]));
                float r = slapy2(g, 1.f);
                g = __fadd_rn(__fsub_rn(d[mm], p),
                              __fdiv_rn(e[l], __fadd_rn(g, copysignf(r, g))));
                float s = 1.f, c = 1.f;
                p = 0.f;
                float csv[2], snv[2];
                for (int i = mm - 1; i >= l; i--) {
                    float f = __fmul_rn(s, e[i]), b = __fmul_rn(c, e[i]);
                    slartg(g, f, &c, &s, &r);
                    if (i != mm - 1) e[i + 1] = r;
                    g = __fsub_rn(d[i + 1], p);
                    r = __fadd_rn(__fmul_rn(__fsub_rn(d[i], g), s),
                                  __fmul_rn(__fmul_rn(2.f, c), b));
                    p = __fmul_rn(s, r);
                    d[i + 1] = __fadd_rn(g, p);
                    g = __fsub_rn(__fmul_rn(c, r), b);
                    csv[i] = c; snv[i] = -s;
                }
                for (int j = mm - 1; j >= l; j--) {
                    float C = csv[j], S = snv[j];
                    for (int k = 0; k < 3; k++) {
                        float tmp = Z[k][j + 1];
                        Z[k][j + 1] = __fsub_rn(__fmul_rn(C, tmp), __fmul_rn(S, Z[k][j]));
                        Z[k][j]     = __fadd_rn(__fmul_rn(S, tmp), __fmul_rn(C, Z[k][j]));
                    }
                }
                d[l] = __fsub_rn(d[l], p); e[l] = g;
            }
        } else {
            for (;;) {
                int mm = lend;
                for (int i = l; i > lend; i--) {
                    float tst = __fmul_rn(e[i - 1], e[i - 1]);
                    if (tst <= __fadd_rn(__fmul_rn(__fmul_rn(eps2, fabsf(d[i])),
                                                   fabsf(d[i - 1])), safmin)) { mm = i; break; }
                }
                if (mm > lend) e[mm - 1] = 0.f;
                float p = d[l];
                if (mm == l) { d[l] = p; l--; if (l >= lend) continue; break; }
                if (mm == l - 1) {
                    float rt1, rt2, c, s;
                    slaev2(d[l - 1], e[l - 1], d[l], &rt1, &rt2, &c, &s);
                    for (int k = 0; k < 3; k++) {
                        float tmp = Z[k][l];
                        Z[k][l]     = __fsub_rn(__fmul_rn(c, tmp), __fmul_rn(s, Z[k][l - 1]));
                        Z[k][l - 1] = __fadd_rn(__fmul_rn(s, tmp), __fmul_rn(c, Z[k][l - 1]));
                    }
                    d[l - 1] = rt1; d[l] = rt2; e[l - 1] = 0.f;
                    l -= 2; if (l >= lend) continue; break;
                }
                if (jtot == nmaxit) break;
                jtot++;
                float g = __fdiv_rn(__fsub_rn(d[l - 1], p), __fmul_rn(2.f, e[l - 1]));
                float r = slapy2(g, 1.f);
                g = __fadd_rn(__fsub_rn(d[mm], p),
                              __fdiv_rn(e[l - 1], __fadd_rn(g, copysignf(r, g))));
                float s = 1.f, c = 1.f;
                p = 0.f;
                float csv[2], snv[2];
                for (int i = mm; i <= l - 1; i++) {
                    float f = __fmul_rn(s, e[i]), b = __fmul_rn(c, e[i]);
                    slartg(g, f, &c, &s, &r);
                    if (i != mm) e[i - 1] = r;
                    g = __fsub_rn(d[i], p);
                    r = __fadd_rn(__fmul_rn(__fsub_rn(d[i + 1], g), s),
                                  __fmul_rn(__fmul_rn(2.f, c), b));
                    p = __fmul_rn(s, r);
                    d[i] = __fadd_rn(g, p);
                    g = __fsub_rn(__fmul_rn(c, r), b);
                    csv[i] = c; snv[i] = s;
                }
                for (int j = mm; j <= l - 1; j++) {
                    float C = csv[j], S = snv[j];
                    for (int k = 0; k < 3; k++) {
                        float tmp = Z[k][j + 1];
                        Z[k][j + 1] = __fsub_rn(__fmul_rn(C, tmp), __fmul_rn(S, Z[k][j]));
                        Z[k][j]     = __fadd_rn(__fmul_rn(S, tmp), __fmul_rn(C, Z[k][j]));
                    }
                }
                d[l] = __fsub_rn(d[l], p); e[l - 1] = g;
            }
        }
    }
    for (int ii = 1; ii < n; ii++) {
        int i = ii - 1, k = i;
        float p = d[i];
        for (int j = ii; j < n; j++) if (d[j] < p) { k = j; p = d[j]; }
        if (k != i) {
            d[k] = d[i]; d[i] = p;
            for (int r2 = 0; r2 < 3; r2++) {
                float t = Z[r2][i]; Z[r2][i] = Z[r2][k]; Z[r2][k] = t;
            }
        }
    }
}

__device__ void eigh3(float a00, float a10, float a11, float a20, float a21, float a22,
                      float V[3][3]) {
    float d[3], e[2], tau, v2;
    d[0] = a00;
    float xnorm = fabsf(a20);
    if (xnorm == 0.f) {
        tau = 0.f; v2 = 0.f;
        e[0] = a10; d[1] = a11; d[2] = a22; e[1] = a21;
    } else {
        float alpha = a10;
        float beta = -copysignf(slapy2(alpha, xnorm), alpha);
        tau = __fdiv_rn(__fsub_rn(beta, alpha), beta);
        v2 = __fmul_rn(a20, __fdiv_rn(1.f, __fsub_rn(alpha, beta)));
        e[0] = beta;
        float w0 = __fmul_rn(tau, __fadd_rn(a11, __fmul_rn(a21, v2)));
        float w1 = __fmul_rn(tau, __fadd_rn(a21, __fmul_rn(a22, v2)));
        float al = __fmul_rn(__fmul_rn(-0.5f, tau), __fadd_rn(w0, __fmul_rn(w1, v2)));
        w0 = __fadd_rn(w0, al);
        w1 = __fadd_rn(w1, __fmul_rn(al, v2));
        d[1] = __fsub_rn(a11, __fmul_rn(2.f, w0));
        e[1] = __fsub_rn(a21, __fadd_rn(__fmul_rn(v2, w0), w1));
        d[2] = __fsub_rn(a22, __fmul_rn(2.f, __fmul_rn(v2, w1)));
    }
    float Z[3][3] = {{1.f,0.f,0.f},{0.f,1.f,0.f},{0.f,0.f,1.f}};
    ssteqr3(d, e, Z);
    if (tau != 0.f) {
        for (int c = 0; c < 3; c++) {
            float dot = __fadd_rn(Z[1][c], __fmul_rn(v2, Z[2][c]));
            float td = __fmul_rn(tau, dot);
            Z[1][c] = __fsub_rn(Z[1][c], td);
            Z[2][c] = __fsub_rn(Z[2][c], __fmul_rn(td, v2));
        }
    }
    for (int r = 0; r < 3; r++)
        for (int c = 0; c < 3; c++) V[r][c] = Z[r][c];
}

// ---------------------------------------------------------------------------
__global__ void k_prep(const float* __restrict__ pos, int n) {
    int i = blockIdx.x * blockDim.x + threadIdx.x;
    if (i < n) {
        float x = pos[3*i], y = pos[3*i+1], z = pos[3*i+2];
        float ss = __fadd_rn(__fadd_rn(__fmul_rn(x,x), __fmul_rn(y,y)), __fmul_rn(z,z));
        g_pts[i] = make_float4(x, y, z, ss);
    }
}

// kNN (warp/query) fused with scale+covariance. Writes g_idx, g_cov.
__global__ __launch_bounds__(256) void k_knn_cov(int Q, int S, int K) {
    __shared__ __align__(16) char sbuf[32768];
    float4* stage = (float4*)sbuf;
    float*  sd = (float*)sbuf;
    int*    si = (int*)(sbuf + 16384);
    int w = threadIdx.x >> 5, lane = threadIdx.x & 31;
    int q = blockIdx.x * 8 + w;
    bool act = (q < Q);
    float qx=0,qy=0,qz=0,qq=0;
    if (act) { float4 p = g_pts[q]; qx=p.x; qy=p.y; qz=p.z; qq=p.w; }
    float bd[KMAX]; int bi[KMAX];
#pragma unroll
    for (int j = 0; j < KMAX; j++) { bd[j]=F_INF; bi[j]=0x7FFFFFFF; }
    for (int t0 = 0; t0 < S; t0 += 1024) {
        int cnt = min(1024, S - t0);
        __syncthreads();
        for (int i = threadIdx.x; i < cnt; i += 256) stage[i] = g_pts[t0 + i];
        __syncthreads();
        if (act) for (int i = lane; i < cnt; i += 32) {
            float4 p = stage[i]; int s = t0 + i;
            float G = __fadd_rn(__fadd_rn(__fmul_rn(qx,p.x), __fmul_rn(qy,p.y)), __fmul_rn(qz,p.z));
            float d = __fsub_rn(__fadd_rn(qq, p.w), __fmul_rn(2.0f, G));
            if (lexless(d, s, bd[KMAX-1], bi[KMAX-1])) {
                float cd = d; int ci = s;
#pragma unroll
                for (int j = 0; j < KMAX; j++)
                    if (lexless(cd, ci, bd[j], bi[j])) {
                        float td=bd[j]; int ti=bi[j]; bd[j]=cd; bi[j]=ci; cd=td; ci=ti;
                    }
            }
        }
    }
    __syncthreads();
    if (!act) return;
    float* swd = sd + w * 512; int* swi = si + w * 512;
#pragma unroll
    for (int j = 0; j < KMAX; j++) { swd[lane*KMAX+j]=bd[j]; swi[lane*KMAX+j]=bi[j]; }
    __syncwarp();
    int ptr = 0;
    int selidx = 0;
    for (int r = 0; r < K; r++) {
        float d = swd[lane*KMAX+ptr]; int i = swi[lane*KMAX+ptr]; int ln = lane;
#pragma unroll
        for (int off = 16; off > 0; off >>= 1) {
            float d2 = __shfl_xor_sync(0xffffffff, d, off);
            int   i2 = __shfl_xor_sync(0xffffffff, i, off);
            int   l2 = __shfl_xor_sync(0xffffffff, ln, off);
            if (lexless(d2, i2, d, i)) { d=d2; i=i2; ln=l2; }
        }
        if (lane == r) selidx = i;                  // lane r keeps neighbor r
        if (lane == ln) { g_idx[q*KMAX+r] = i; ptr++; }
        __syncwarp();
    }
    // --- scale + covariance (identical arithmetic to R13 k_geom) ---
    float rx=0, ry=0, rz=0, nrm=0;
    if (lane < K) {
        float4 p = g_pts[selidx];
        rx = __fsub_rn(p.x, qx);
        ry = __fsub_rn(p.y, qy);
        rz = __fsub_rn(p.z, qz);
        nrm = __fsqrt_rn(__fadd_rn(__fadd_rn(__fmul_rn(rx,rx),__fmul_rn(ry,ry)),__fmul_rn(rz,rz)));
    }
    float mx = nrm;
#pragma unroll
    for (int off = 16; off > 0; off >>= 1) mx = fmaxf(mx, __shfl_xor_sync(0xffffffff, mx, off));
    float den = __fadd_rn(mx, 1e-8f);
    if (lane < K) { rx=__fdiv_rn(rx,den); ry=__fdiv_rn(ry,den); rz=__fdiv_rn(rz,den); }
    else { rx=ry=rz=0.f; }
    float c00=__fmul_rn(rx,rx), c01=__fmul_rn(rx,ry), c02=__fmul_rn(rx,rz);
    float c11=__fmul_rn(ry,ry), c12=__fmul_rn(ry,rz), c22=__fmul_rn(rz,rz);
#pragma unroll
    for (int off = 16; off > 0; off >>= 1) {
        c00=__fadd_rn(c00,__shfl_xor_sync(0xffffffff,c00,off));
        c01=__fadd_rn(c01,__shfl_xor_sync(0xffffffff,c01,off));
        c02=__fadd_rn(c02,__shfl_xor_sync(0xffffffff,c02,off));
        c11=__fadd_rn(c11,__shfl_xor_sync(0xffffffff,c11,off));
        c12=__fadd_rn(c12,__shfl_xor_sync(0xffffffff,c12,off));
        c22=__fadd_rn(c22,__shfl_xor_sync(0xffffffff,c22,off));
    }
    if (lane == 0) {
        float fk=(float)K;
        g_cov[q*6+0]=__fdiv_rn(c00,fk); g_cov[q*6+1]=__fdiv_rn(c01,fk);
        g_cov[q*6+2]=__fdiv_rn(c02,fk); g_cov[q*6+3]=__fdiv_rn(c11,fk);
        g_cov[q*6+4]=__fdiv_rn(c12,fk); g_cov[q*6+5]=__fdiv_rn(c22,fk);
    }
}

// eigh: one thread per query (TLP hides serial/local-mem latency)
__global__ void k_eigh(int Q) {
    int q = blockIdx.x * blockDim.x + threadIdx.x;
    if (q >= Q) return;
    float a00=g_cov[q*6+0], a01=g_cov[q*6+1], a02=g_cov[q*6+2];
    float a11=g_cov[q*6+3], a12=g_cov[q*6+4], a22=g_cov[q*6+5];
    float V[3][3];
    eigh3(a00, a01, a11, a02, a12, a22, V);
#pragma unroll
    for (int r = 0; r < 3; r++)
#pragma unroll
        for (int c = 0; c < 3; c++) g_V[q*9 + r*3 + c] = V[r][c];
}

// phi: warp per query — recompute normalized r, rotate by V, 45-basis
__global__ __launch_bounds__(256) void k_phi(int Q, int K) {
    int w = threadIdx.x >> 5, lane = threadIdx.x & 31;
    int q = blockIdx.x * 8 + w;
    if (q >= Q) return;
    float4 qp = g_pts[q];
    float rx=0, ry=0, rz=0, nrm=0;
    if (lane < K) {
        int s = g_idx[q*KMAX+lane];
        float4 p = g_pts[s];
        rx = __fsub_rn(p.x, qp.x);
        ry = __fsub_rn(p.y, qp.y);
        rz = __fsub_rn(p.z, qp.z);
        nrm = __fsqrt_rn(__fadd_rn(__fadd_rn(__fmul_rn(rx,rx),__fmul_rn(ry,ry)),__fmul_rn(rz,rz)));
    }
    float mx = nrm;
#pragma unroll
    for (int off = 16; off > 0; off >>= 1) mx = fmaxf(mx, __shfl_xor_sync(0xffffffff, mx, off));
    float den = __fadd_rn(mx, 1e-8f);
    if (lane < K) {
        rx=__fdiv_rn(rx,den); ry=__fdiv_rn(ry,den); rz=__fdiv_rn(rz,den);
        float v00=g_V[q*9+0], v01=g_V[q*9+1], v02=g_V[q*9+2];
        float v10=g_V[q*9+3], v11=g_V[q*9+4], v12=g_V[q*9+5];
        float v20=g_V[q*9+6], v21=g_V[q*9+7], v22=g_V[q*9+8];
        float X=__fmaf_rn(rz,v20,__fmaf_rn(ry,v10,__fmul_rn(rx,v00)));
        float Y=__fmaf_rn(rz,v21,__fmaf_rn(ry,v11,__fmul_rn(rx,v01)));
        float Z=__fmaf_rn(rz,v22,__fmaf_rn(ry,v12,__fmul_rn(rx,v02)));
        float px[5], py[3], pz[3];
        px[0]=1.f; px[1]=X; px[2]=__fmul_rn(X,X); px[3]=__fmul_rn(px[2],X); px[4]=__fmul_rn(px[3],X);
        py[0]=1.f; py[1]=Y; py[2]=__fmul_rn(Y,Y);
        pz[0]=1.f; pz[1]=Z; pz[2]=__fmul_rn(Z,Z);
        float* dst = g_phi + (q*KMAX+lane)*45;
#pragma unroll
        for (int n = 0; n < 5; n++)
#pragma unroll
            for (int l = 0; l < 3; l++)
#pragma unroll
                for (int m = 0; m < 3; m++)
                    dst[n*9+l*3+m] = __fmul_rn(__fmul_rn(px[n],py[l]),pz[m]);
    }
}

// t[q] = (phi^T nf)/k — coalesced single-round gather
__global__ __launch_bounds__(128) void k_tker(int K, int C, const float* __restrict__ nf,
                                              float* __restrict__ tout) {
    __shared__ int   sidx[KMAX];
    __shared__ float sphi[KMAX*45];
    __shared__ float snf[KMAX*256];
    int q = blockIdx.x, tid = threadIdx.x;
    if (tid < K) sidx[tid] = g_idx[q*KMAX+tid];
    for (int e = tid; e < K*45; e += 128) sphi[e] = g_phi[q*KMAX*45 + e];
    __syncthreads();
    for (int e = tid; e < K*C; e += 128) {
        int kk = e / C, c = e - kk*C;
        snf[e] = nf[sidx[kk]*C + c];
    }
    __syncthreads();
    int E = 45*C; float fk = (float)K;
    for (int e = tid; e < E; e += 128) {
        int b = e / C, c = e - b*C;
        float acc = 0.f;
        for (int kk = 0; kk < K; kk++)
            acc = __fmaf_rn(sphi[kk*45+b], snf[kk*C+c], acc);
        tout[q*E+e] = __fdiv_rn(acc, fk);
    }
}

// plain GEMM: out = epi(X@W), epi: +bias, +addin, relu. N%64==0
__global__ __launch_bounds__(128) void k_gemm(int M, int N, int K,
                                              const float* __restrict__ X,
                                              const float* __restrict__ W,
                                              const float* __restrict__ bias,
                                              const float* __restrict__ addin,
                                              float* __restrict__ out, int relu) {
    __shared__ float Xs[16][33];
    __shared__ __align__(16) float Ws[32][64];
    int m0 = blockIdx.x*16, n0 = blockIdx.y*64;
    int tid = threadIdx.x, tn = tid & 15, tm = tid >> 4;
    float acc[2][4] = {};
    for (int k0 = 0; k0 < K; k0 += 32) {
#pragma unroll
        for (int j = 0; j < 4; j++) {
            int id = tid*4+j, r = id>>5, c = id&31;
            float v = 0.f;
            if (m0+r < M && k0+c < K) v = X[(m0+r)*K + k0+c];
            Xs[r][c] = v;
        }
#pragma unroll
        for (int j = 0; j < 16; j++) {
            int id = tid + j*128, r = id>>6, c = id&63;
            float v = 0.f;
            if (k0+r < K) v = W[(k0+r)*N + n0+c];
            Ws[r][c] = v;
        }
        __syncthreads();
#pragma unroll
        for (int kk = 0; kk < 32; kk++) {
            float a0 = Xs[tm*2][kk], a1 = Xs[tm*2+1][kk];
            float4 b = *(const float4*)&Ws[kk][tn*4];
            acc[0][0]=__fmaf_rn(a0,b.x,acc[0][0]); acc[0][1]=__fmaf_rn(a0,b.y,acc[0][1]);
            acc[0][2]=__fmaf_rn(a0,b.z,acc[0][2]); acc[0][3]=__fmaf_rn(a0,b.w,acc[0][3]);
            acc[1][0]=__fmaf_rn(a1,b.x,acc[1][0]); acc[1][1]=__fmaf_rn(a1,b.y,acc[1][1]);
            acc[1][2]=__fmaf_rn(a1,b.z,acc[1][2]); acc[1][3]=__fmaf_rn(a1,b.w,acc[1][3]);
        }
        __syncthreads();
    }
#pragma unroll
    for (int i = 0; i < 2; i++) {
        int m = m0 + tm*2 + i;
        if (m < M)
#pragma unroll
            for (int j = 0; j < 4; j++) {
                int n = n0 + tn*4 + j;
                float y = acc[i][j];
                if (bias)  y = __fadd_rn(y, bias[n]);
                if (addin) y = __fadd_rn(addin[m*N+n], y);
                if (relu)  y = fmaxf(y, 0.f);
                out[m*N+n] = y;
            }
    }
}

// split-K GEMM: partials to part[z][m*N+n]; Kc = chunk size
__global__ __launch_bounds__(128) void k_gemm_sk(int M, int N, int K, int Kc,
                                                 const float* __restrict__ X,
                                                 const float* __restrict__ W,
                                                 float* __restrict__ part) {
    __shared__ float Xs[16][33];
    __shared__ __align__(16) float Ws[32][64];
    int m0 = blockIdx.x*16, n0 = blockIdx.y*64, z = blockIdx.z;
    int kbeg = z * Kc, kend = min(K, kbeg + Kc);
    int tid = threadIdx.x, tn = tid & 15, tm = tid >> 4;
    float acc[2][4] = {};
    for (int k0 = kbeg; k0 < kend; k0 += 32) {
#pragma unroll
        for (int j = 0; j < 4; j++) {
            int id = tid*4+j, r = id>>5, c = id&31;
            float v = 0.f;
            if (m0+r < M && k0+c < kend) v = X[(m0+r)*K + k0+c];
            Xs[r][c] = v;
        }
#pragma unroll
        for (int j = 0; j < 16; j++) {
            int id = tid + j*128, r = id>>6, c = id&63;
            float v = 0.f;
            if (k0+r < kend) v = W[(k0+r)*N + n0+c];
            Ws[r][c] = v;
        }
        __syncthreads();
#pragma unroll
        for (int kk = 0; kk < 32; kk++) {
            float a0 = Xs[tm*2][kk], a1 = Xs[tm*2+1][kk];
            float4 b = *(const float4*)&Ws[kk][tn*4];
            acc[0][0]=__fmaf_rn(a0,b.x,acc[0][0]); acc[0][1]=__fmaf_rn(a0,b.y,acc[0][1]);
            acc[0][2]=__fmaf_rn(a0,b.z,acc[0][2]); acc[0][3]=__fmaf_rn(a0,b.w,acc[0][3]);
            acc[1][0]=__fmaf_rn(a1,b.x,acc[1][0]); acc[1][1]=__fmaf_rn(a1,b.y,acc[1][1]);
            acc[1][2]=__fmaf_rn(a1,b.z,acc[1][2]); acc[1][3]=__fmaf_rn(a1,b.w,acc[1][3]);
        }
        __syncthreads();
    }
    float* dst = part + (size_t)z * M * N;
#pragma unroll
    for (int i = 0; i < 2; i++) {
        int m = m0 + tm*2 + i;
        if (m < M)
#pragma unroll
            for (int j = 0; j < 4; j++) {
                int n = n0 + tn*4 + j;
                dst[m*N+n] = acc[i][j];
            }
    }
}

// deterministic sequential-z reduction + bias + relu
__global__ void k_reduce(int MN, int N, int S, const float* __restrict__ part,
                         const float* __restrict__ bias, float* __restrict__ out) {
    int i = blockIdx.x*256 + threadIdx.x;
    if (i >= MN) return;
    float acc = part[i];
    for (int z = 1; z < S; z++) acc = __fadd_rn(acc, part[(size_t)z*MN + i]);
    acc = __fadd_rn(acc, bias[i % N]);
    out[i] = fmaxf(acc, 0.f);
}

__global__ __launch_bounds__(128) void k_head(const float* __restrict__ hw,
                                              const float* __restrict__ hb,
                                              float* __restrict__ out) {
    __shared__ float red[128];
    int tid = threadIdx.x;
    float acc = 0.f;
    for (int i = tid; i < 512; i += 128)
        acc = __fmaf_rn(g_f4[i], hw[i], acc);
    red[tid] = acc;
    __syncthreads();
    for (int s = 64; s > 0; s >>= 1) {
        if (tid < s) red[tid] = __fadd_rn(red[tid], red[tid+s]);
        __syncthreads();
    }
    if (tid == 0) out[0] = __fadd_rn(red[0], hb[0]);
}

extern "C" void kernel_launch(void* const* d_in, const int* in_sizes, int n_in,
                              void* d_out, int out_size) {
    const float* pos  = (const float*)d_in[0];
    const float* chan = (const float*)d_in[1];
    const float* w[7]; const float* b[7];
    for (int li = 0; li < 7; li++) { w[li] = (const float*)d_in[2+2*li]; b[li] = (const float*)d_in[3+2*li]; }
    const float* p1 = (const float*)d_in[16];
    const float* p2 = (const float*)d_in[17];
    const float* p3 = (const float*)d_in[18];
    const float* p4 = (const float*)d_in[19];
    const float* hw = (const float*)d_in[20];
    const float* hb = (const float*)d_in[21];
    float* out = (float*)d_out;

    void* pv;
    cudaGetSymbolAddress(&pv, g_t);    float* tp  = (float*)pv;
    cudaGetSymbolAddress(&pv, g_xa);   float* xa  = (float*)pv;
    cudaGetSymbolAddress(&pv, g_xb);   float* xb  = (float*)pv;
    cudaGetSymbolAddress(&pv, g_f1);   float* f1  = (float*)pv;
    cudaGetSymbolAddress(&pv, g_f2);   float* f2  = (float*)pv;
    cudaGetSymbolAddress(&pv, g_f3);   float* f3  = (float*)pv;
    cudaGetSymbolAddress(&pv, g_f4);   float* f4  = (float*)pv;
    cudaGetSymbolAddress(&pv, g_part); float* pp  = (float*)pv;

    k_prep<<<(NPTS+255)/256, 256>>>(pos, NPTS);

    // L1: Q=2435 S=32768 k=16 Cin=4 -> 64  (K=180: plain gemm)
    k_knn_cov<<<(2435+7)/8, 256>>>(2435, NPTS, 16);
    k_eigh<<<(2435+255)/256, 256>>>(2435);
    k_phi<<<(2435+7)/8, 256>>>(2435, 16);
    k_tker<<<2435, 128>>>(16, 4, chan, tp);
    k_gemm<<<dim3((2435+15)/16, 1), 128>>>(2435, 64, 180, tp, w[0], b[0], nullptr, xa, 1);

    // L2: Q=2435 S=2435 k=16 Cin=64 -> 64  (K=2880: split 4)
    k_knn_cov<<<(2435+7)/8, 256>>>(2435, 2435, 16);
    k_eigh<<<(2435+255)/256, 256>>>(2435);
    k_phi<<<(2435+7)/8, 256>>>(2435, 16);
    k_tker<<<2435, 128>>>(16, 64, xa, tp);
    k_gemm_sk<<<dim3((2435+15)/16, 1, 4), 128>>>(2435, 64, 2880, 720, tp, w[1], pp);
    k_reduce<<<(2435*64+255)/256, 256>>>(2435*64, 64, 4, pp, b[1], xb);
    k_gemm<<<dim3((2435+15)/16, 1), 128>>>(2435, 64, 4, chan, p1, nullptr, xb, f1, 1);

    // L3: Q=181 S=2435 k=16 Cin=64 -> 128  (K=2880: split 8)
    k_knn_cov<<<(181+7)/8, 256>>>(181, 2435, 16);
    k_eigh<<<1, 256>>>(181);
    k_phi<<<(181+7)/8, 256>>>(181, 16);
    k_tker<<<181, 128>>>(16, 64, f1, tp);
    k_gemm_sk<<<dim3((181+15)/16, 2, 8), 128>>>(181, 128, 2880, 360, tp, w[2], pp);
    k_reduce<<<(181*128+255)/256, 256>>>(181*128, 128, 8, pp, b[2], xa);

    // L4: Q=181 S=181 k=16 Cin=128 -> 128  (K=5760: split 8)
    k_knn_cov<<<(181+7)/8, 256>>>(181, 181, 16);
    k_eigh<<<1, 256>>>(181);
    k_phi<<<(181+7)/8, 256>>>(181, 16);
    k_tker<<<181, 128>>>(16, 128, xa, tp);
    k_gemm_sk<<<dim3((181+15)/16, 2, 8), 128>>>(181, 128, 5760, 720, tp, w[3], pp);
    k_reduce<<<(181*128+255)/256, 256>>>(181*128, 128, 8, pp, b[3], xb);
    k_gemm<<<dim3((181+15)/16, 2), 128>>>(181, 128, 64, f1, p2, nullptr, xb, f2, 1);

    // L5: Q=13 S=181 k=16 Cin=128 -> 256  (K=5760: split 16)
    k_knn_cov<<<2, 256>>>(13, 181, 16);
    k_eigh<<<1, 256>>>(13);
    k_phi<<<2, 256>>>(13, 16);
    k_tker<<<13, 128>>>(16, 128, f2, tp);
    k_gemm_sk<<<dim3(1, 4, 16), 128>>>(13, 256, 5760, 360, tp, w[4], pp);
    k_reduce<<<(13*256+255)/256, 256>>>(13*256, 256, 16, pp, b[4], xa);

    // L6: Q=13 S=13 k=13 Cin=256 -> 256  (K=11520: split 32)
    k_knn_cov<<<2, 256>>>(13, 13, 13);
    k_eigh<<<1, 256>>>(13);
    k_phi<<<2, 256>>>(13, 13);
    k_tker<<<13, 128>>>(13, 256, xa, tp);
    k_gemm_sk<<<dim3(1, 4, 32), 128>>>(13, 256, 11520, 360, tp, w[5], pp);
    k_reduce<<<(13*256+255)/256, 256>>>(13*256, 256, 32, pp, b[5], xb);
    k_gemm<<<dim3(1, 4), 128>>>(13, 256, 128, f2, p3, nullptr, xb, f3, 1);

    // L7: Q=1 S=13 k=13 Cin=256 -> 512  (K=11520: split 32)
    k_knn_cov<<<1, 256>>>(1, 13, 13);
    k_eigh<<<1, 256>>>(1);
    k_phi<<<1, 256>>>(1, 13);
    k_tker<<<1, 128>>>(13, 256, f3, tp);
    k_gemm_sk<<<dim3(1, 8, 32), 128>>>(1, 512, 11520, 360, tp, w[6], pp);
    k_reduce<<<2, 256>>>(512, 512, 32, pp, b[6], xa);
    k_gemm<<<dim3(1, 8), 128>>>(1, 512, 256, f3, p4, nullptr, xa, f4, 1);

    k_head<<<1, 128>>>(hw, hb, out);
}

// round 15
// speedup vs baseline: 2.1214x; 1.1221x over previous
#include <cuda_runtime.h>
#include <cstdint>

#define KMAX 16
#define NPTS 32768
#define N1 2435

__device__ float4 g_pts[NPTS];
__device__ int    g_idx[N1 * KMAX];
__device__ float  g_cov[N1 * 6];
__device__ float  g_t[N1 * 45 * 64];
__device__ float  g_xa[N1 * 64];
__device__ float  g_f1[N1 * 64];
__device__ float  g_f2[181 * 128];
__device__ float  g_f3[13 * 256];
__device__ float  g_f4[512];
__device__ float  g_part[4 * N1 * 64];   // split-K partials

__device__ __forceinline__ bool lexless(float d1, int i1, float d2, int i2) {
    return (d1 < d2) || (d1 == d2 && i1 < i2);
}
#define F_INF __int_as_float(0x7f800000)

// ---------------------------------------------------------------------------
// LAPACK-faithful 3x3 symmetric eigendecomposition (verified R13 — DO NOT MODIFY)
// ---------------------------------------------------------------------------
__device__ __forceinline__ float slapy2(float x, float y) {
    float xa = fabsf(x), ya = fabsf(y);
    float w = fmaxf(xa, ya), z = fminf(xa, ya);
    if (z == 0.f) return w;
    float q = __fdiv_rn(z, w);
    return __fmul_rn(w, __fsqrt_rn(__fadd_rn(1.f, __fmul_rn(q, q))));
}

__device__ void slaev2(float a, float b, float c,
                       float* rt1, float* rt2, float* cs1, float* sn1) {
    float sm = __fadd_rn(a, c), df = __fsub_rn(a, c), adf = fabsf(df);
    float tb = __fadd_rn(b, b), ab = fabsf(tb);
    float acmx, acmn;
    if (fabsf(a) > fabsf(c)) { acmx = a; acmn = c; } else { acmx = c; acmn = a; }
    float rt;
    if (adf > ab) {
        float q = __fdiv_rn(ab, adf);
        rt = __fmul_rn(adf, __fsqrt_rn(__fadd_rn(1.f, __fmul_rn(q, q))));
    } else if (adf < ab) {
        float q = __fdiv_rn(adf, ab);
        rt = __fmul_rn(ab, __fsqrt_rn(__fadd_rn(1.f, __fmul_rn(q, q))));
    } else {
        rt = __fmul_rn(ab, __fsqrt_rn(2.f));
    }
    int sgn1;
    if (sm < 0.f) {
        *rt1 = __fmul_rn(0.5f, __fsub_rn(sm, rt)); sgn1 = -1;
        *rt2 = __fsub_rn(__fmul_rn(__fdiv_rn(acmx, *rt1), acmn),
                         __fmul_rn(__fdiv_rn(b, *rt1), b));
    } else if (sm > 0.f) {
        *rt1 = __fmul_rn(0.5f, __fadd_rn(sm, rt)); sgn1 = 1;
        *rt2 = __fsub_rn(__fmul_rn(__fdiv_rn(acmx, *rt1), acmn),
                         __fmul_rn(__fdiv_rn(b, *rt1), b));
    } else {
        *rt1 = __fmul_rn(0.5f, rt); *rt2 = __fmul_rn(-0.5f, rt); sgn1 = 1;
    }
    float cs; int sgn2;
    if (df >= 0.f) { cs = __fadd_rn(df, rt); sgn2 = 1; }
    else           { cs = __fsub_rn(df, rt); sgn2 = -1; }
    float acs = fabsf(cs);
    if (acs > ab) {
        float ct = __fdiv_rn(-tb, cs);
        *sn1 = __fdiv_rn(1.f, __fsqrt_rn(__fadd_rn(1.f, __fmul_rn(ct, ct))));
        *cs1 = __fmul_rn(ct, *sn1);
    } else {
        if (ab == 0.f) { *cs1 = 1.f; *sn1 = 0.f; }
        else {
            float tn = __fdiv_rn(-cs, tb);
            *cs1 = __fdiv_rn(1.f, __fsqrt_rn(__fadd_rn(1.f, __fmul_rn(tn, tn))));
            *sn1 = __fmul_rn(tn, *cs1);
        }
    }
    if (sgn1 == sgn2) { float tn = *cs1; *cs1 = -*sn1; *sn1 = tn; }
}

__device__ __forceinline__ void slartg(float f, float g, float* c, float* s, float* r) {
    if (g == 0.f) { *c = 1.f; *s = 0.f; *r = f; }
    else if (f == 0.f) { *c = 0.f; *s = (g > 0.f ? 1.f : -1.f); *r = fabsf(g); }
    else {
        float d = __fsqrt_rn(__fadd_rn(__fmul_rn(f, f), __fmul_rn(g, g)));
        *c = __fdiv_rn(fabsf(f), d);
        *r = (f > 0.f ? d : -d);
        *s = __fdiv_rn(g, *r);
    }
}

__device__ void ssteqr3(float d[3], float e[2], float Z[3][3]) {
    const float eps = 5.9604645e-8f;
    const float eps2 = eps * eps;
    const float safmin = 1.17549435e-38f;
    const int n = 3, nmaxit = 90;
    int jtot = 0, l1 = 0;
    while (l1 < n) {
        if (l1 > 0) e[l1 - 1] = 0.f;
        int m;
        for (m = l1; m < n - 1; m++) {
            float tst = fabsf(e[m]);
            if (tst == 0.f) break;
            if (tst <= __fmul_rn(__fmul_rn(__fsqrt_rn(fabsf(d[m])),
                                           __fsqrt_rn(fabsf(d[m + 1]))), eps)) {
                e[m] = 0.f; break;
            }
        }
        int l = l1, lend = m;
        l1 = m + 1;
        if (lend == l) continue;
        if (fabsf(d[lend]) < fabsf(d[l])) { int t = l; l = lend; lend = t; }
        if (lend > l) {
            for (;;) {
                int mm = lend;
                for (int i = l; i < lend; i++) {
                    float tst = __fmul_rn(e[i], e[i]);
                    if (tst <= __fadd_rn(__fmul_rn(__fmul_rn(eps2, fabsf(d[i])),
                                                   fabsf(d[i + 1])), safmin)) { mm = i; break; }
                }
                if (mm < lend) e[mm] = 0.f;
                float p = d[l];
                if (mm == l) { d[l] = p; l++; if (l <= lend) continue; break; }
                if (mm == l + 1) {
                    float rt1, rt2, c, s;
                    slaev2(d[l], e[l], d[l + 1], &rt1, &rt2, &c, &s);
                    for (int k = 0; k < 3; k++) {
                        float tmp = Z[k][l + 1];
                        Z[k][l + 1] = __fsub_rn(__fmul_rn(c, tmp), __fmul_rn(s, Z[k][l]));
                        Z[k][l]     = __fadd_rn(__fmul_rn(s, tmp), __fmul_rn(c, Z[k][l]));
                    }
                    d[l] = rt1; d[l + 1] = rt2; e[l] = 0.f;
                    l += 2; if (l <= lend) continue; break;
                }
                if (jtot == nmaxit) break;
                jtot++;
                float g = __fdiv_rn(__fsub_rn(d[l + 1], p), __fmul_rn(2.f, e[l]));
                float r = slapy2(g, 1.f);
                g = __fadd_rn(__fsub_rn(d[mm], p),
                              __fdiv_rn(e[l], __fadd_rn(g, copysignf(r, g))));
                float s = 1.f, c = 1.f;
                p = 0.f;
                float csv[2], snv[2];
                for (int i = mm - 1; i >= l; i--) {
                    float f = __fmul_rn(s, e[i]), b = __fmul_rn(c, e[i]);
                    slartg(g, f, &c, &s, &r);
                    if (i != mm - 1) e[i + 1] = r;
                    g = __fsub_rn(d[i + 1], p);
                    r = __fadd_rn(__fmul_rn(__fsub_rn(d[i], g), s),
                                  __fmul_rn(__fmul_rn(2.f, c), b));
                    p = __fmul_rn(s, r);
                    d[i + 1] = __fadd_rn(g, p);
                    g = __fsub_rn(__fmul_rn(c, r), b);
                    csv[i] = c; snv[i] = -s;
                }
                for (int j = mm - 1; j >= l; j--) {
                    float C = csv[j], S = snv[j];
                    for (int k = 0; k < 3; k++) {
                        float tmp = Z[k][j + 1];
                        Z[k][j + 1] = __fsub_rn(__fmul_rn(C, tmp), __fmul_rn(S, Z[k][j]));
                        Z[k][j]     = __fadd_rn(__fmul_rn(S, tmp), __fmul_rn(C, Z[k][j]));
                    }
                }
                d[l] = __fsub_rn(d[l], p); e[l] = g;
            }
        } else {
            for (;;) {
                int mm = lend;
                for (int i = l; i > lend; i--) {
                    float tst = __fmul_rn(e[i - 1], e[i - 1]);
                    if (tst <= __fadd_rn(__fmul_rn(__fmul_rn(eps2, fabsf(d[i])),
                                                   fabsf(d[i - 1])), safmin)) { mm = i; break; }
                }
                if (mm > lend) e[mm - 1] = 0.f;
                float p = d[l];
                if (mm == l) { d[l] = p; l--; if (l >= lend) continue; break; }
                if (mm == l - 1) {
                    float rt1, rt2, c, s;
                    slaev2(d[l - 1], e[l - 1], d[l], &rt1, &rt2, &c, &s);
                    for (int k = 0; k < 3; k++) {
                        float tmp = Z[k][l];
                        Z[k][l]     = __fsub_rn(__fmul_rn(c, tmp), __fmul_rn(s, Z[k][l - 1]));
                        Z[k][l - 1] = __fadd_rn(__fmul_rn(s, tmp), __fmul_rn(c, Z[k][l - 1]));
                    }
                    d[l - 1] = rt1; d[l] = rt2; e[l - 1] = 0.f;
                    l -= 2; if (l >= lend) continue; break;
                }
                if (jtot == nmaxit) break;
                jtot++;
                float g = __fdiv_rn(__fsub_rn(d[l - 1], p), __fmul_rn(2.f, e[l - 1]));
                float r = slapy2(g, 1.f);
                g = __fadd_rn(__fsub_rn(d[mm], p),
                              __fdiv_rn(e[l - 1], __fadd_rn(g, copysignf(r, g))));
                float s = 1.f, c = 1.f;
                p = 0.f;
                float csv[2], snv[2];
                for (int i = mm; i <= l - 1; i++) {
                    float f = __fmul_rn(s, e[i]), b = __fmul_rn(c, e[i]);
                    slartg(g, f, &c, &s, &r);
                    if (i != mm) e[i - 1] = r;
                    g = __fsub_rn(d[i], p);
                    r = __fadd_rn(__fmul_rn(__fsub_rn(d[i + 1], g), s),
                                  __fmul_rn(__fmul_rn(2.f, c), b));
                    p = __fmul_rn(s, r);
                    d[i] = __fadd_rn(g, p);
                    g = __fsub_rn(__fmul_rn(c, r), b);
                    csv[i] = c; snv[i] = s;
                }
                for (int j = mm; j <= l - 1; j++) {
                    float C = csv[j], S = snv[j];
                    for (int k = 0; k < 3; k++) {
                        float tmp = Z[k][j + 1];
                        Z[k][j + 1] = __fsub_rn(__fmul_rn(C, tmp), __fmul_rn(S, Z[k][j]));
                        Z[k][j]     = __fadd_rn(__fmul_rn(S, tmp), __fmul_rn(C, Z[k][j]));
                    }
                }
                d[l] = __fsub_rn(d[l], p); e[l - 1] = g;
            }
        }
    }
    for (int ii = 1; ii < n; ii++) {
        int i = ii - 1, k = i;
        float p = d[i];
        for (int j = ii; j < n; j++) if (d[j] < p) { k = j; p = d[j]; }
        if (k != i) {
            d[k] = d[i]; d[i] = p;
            for (int r2 = 0; r2 < 3; r2++) {
                float t = Z[r2][i]; Z[r2][i] = Z[r2][k]; Z[r2][k] = t;
            }
        }
    }
}

__device__ void eigh3(float a00, float a10, float a11, float a20, float a21, float a22,
                      float V[3][3]) {
    float d[3], e[2], tau, v2;
    d[0] = a00;
    float xnorm = fabsf(a20);
    if (xnorm == 0.f) {
        tau = 0.f; v2 = 0.f;
        e[0] = a10; d[1] = a11; d[2] = a22; e[1] = a21;
    } else {
        float alpha = a10;
        float beta = -copysignf(slapy2(alpha, xnorm), alpha);
        tau = __fdiv_rn(__fsub_rn(beta, alpha), beta);
        v2 = __fmul_rn(a20, __fdiv_rn(1.f, __fsub_rn(alpha, beta)));
        e[0] = beta;
        float w0 = __fmul_rn(tau, __fadd_rn(a11, __fmul_rn(a21, v2)));
        float w1 = __fmul_rn(tau, __fadd_rn(a21, __fmul_rn(a22, v2)));
        float al = __fmul_rn(__fmul_rn(-0.5f, tau), __fadd_rn(w0, __fmul_rn(w1, v2)));
        w0 = __fadd_rn(w0, al);
        w1 = __fadd_rn(w1, __fmul_rn(al, v2));
        d[1] = __fsub_rn(a11, __fmul_rn(2.f, w0));
        e[1] = __fsub_rn(a21, __fadd_rn(__fmul_rn(v2, w0), w1));
        d[2] = __fsub_rn(a22, __fmul_rn(2.f, __fmul_rn(v2, w1)));
    }
    float Z[3][3] = {{1.f,0.f,0.f},{0.f,1.f,0.f},{0.f,0.f,1.f}};
    ssteqr3(d, e, Z);
    if (tau != 0.f) {
        for (int c = 0; c < 3; c++) {
            float dot = __fadd_rn(Z[1][c], __fmul_rn(v2, Z[2][c]));
            float td = __fmul_rn(tau, dot);
            Z[1][c] = __fsub_rn(Z[1][c], td);
            Z[2][c] = __fsub_rn(Z[2][c], __fmul_rn(td, v2));
        }
    }
    for (int r = 0; r < 3; r++)
        for (int c = 0; c < 3; c++) V[r][c] = Z[r][c];
}

// ---------------------------------------------------------------------------
__global__ void k_prep(const float* __restrict__ pos, int n) {
    int i = blockIdx.x * blockDim.x + threadIdx.x;
    if (i < n) {
        float x = pos[3*i], y = pos[3*i+1], z = pos[3*i+2];
        float ss = __fadd_rn(__fadd_rn(__fmul_rn(x,x), __fmul_rn(y,y)), __fmul_rn(z,z));
        g_pts[i] = make_float4(x, y, z, ss);
    }
}

// kNN (warp/query) fused with scale+covariance. Writes g_idx, g_cov.
__global__ __launch_bounds__(256) void k_knn_cov(int Q, int S, int K) {
    __shared__ __align__(16) char sbuf[32768];
    float4* stage = (float4*)sbuf;
    float*  sd = (float*)sbuf;
    int*    si = (int*)(sbuf + 16384);
    int w = threadIdx.x >> 5, lane = threadIdx.x & 31;
    int q = blockIdx.x * 8 + w;
    bool act = (q < Q);
    float qx=0,qy=0,qz=0,qq=0;
    if (act) { float4 p = g_pts[q]; qx=p.x; qy=p.y; qz=p.z; qq=p.w; }
    float bd[KMAX]; int bi[KMAX];
#pragma unroll
    for (int j = 0; j < KMAX; j++) { bd[j]=F_INF; bi[j]=0x7FFFFFFF; }
    for (int t0 = 0; t0 < S; t0 += 1024) {
        int cnt = min(1024, S - t0);
        __syncthreads();
        for (int i = threadIdx.x; i < cnt; i += 256) stage[i] = g_pts[t0 + i];
        __syncthreads();
        if (act) for (int i = lane; i < cnt; i += 32) {
            float4 p = stage[i]; int s = t0 + i;
            float G = __fadd_rn(__fadd_rn(__fmul_rn(qx,p.x), __fmul_rn(qy,p.y)), __fmul_rn(qz,p.z));
            float d = __fsub_rn(__fadd_rn(qq, p.w), __fmul_rn(2.0f, G));
            if (lexless(d, s, bd[KMAX-1], bi[KMAX-1])) {
                float cd = d; int ci = s;
#pragma unroll
                for (int j = 0; j < KMAX; j++)
                    if (lexless(cd, ci, bd[j], bi[j])) {
                        float td=bd[j]; int ti=bi[j]; bd[j]=cd; bi[j]=ci; cd=td; ci=ti;
                    }
            }
        }
    }
    __syncthreads();
    if (!act) return;
    float* swd = sd + w * 512; int* swi = si + w * 512;
#pragma unroll
    for (int j = 0; j < KMAX; j++) { swd[lane*KMAX+j]=bd[j]; swi[lane*KMAX+j]=bi[j]; }
    __syncwarp();
    int ptr = 0;
    int selidx = 0;
    for (int r = 0; r < K; r++) {
        float d = swd[lane*KMAX+ptr]; int i = swi[lane*KMAX+ptr]; int ln = lane;
#pragma unroll
        for (int off = 16; off > 0; off >>= 1) {
            float d2 = __shfl_xor_sync(0xffffffff, d, off);
            int   i2 = __shfl_xor_sync(0xffffffff, i, off);
            int   l2 = __shfl_xor_sync(0xffffffff, ln, off);
            if (lexless(d2, i2, d, i)) { d=d2; i=i2; ln=l2; }
        }
        if (lane == r) selidx = i;
        if (lane == ln) { g_idx[q*KMAX+r] = i; ptr++; }
        __syncwarp();
    }
    float rx=0, ry=0, rz=0, nrm=0;
    if (lane < K) {
        float4 p = g_pts[selidx];
        rx = __fsub_rn(p.x, qx);
        ry = __fsub_rn(p.y, qy);
        rz = __fsub_rn(p.z, qz);
        nrm = __fsqrt_rn(__fadd_rn(__fadd_rn(__fmul_rn(rx,rx),__fmul_rn(ry,ry)),__fmul_rn(rz,rz)));
    }
    float mx = nrm;
#pragma unroll
    for (int off = 16; off > 0; off >>= 1) mx = fmaxf(mx, __shfl_xor_sync(0xffffffff, mx, off));
    float den = __fadd_rn(mx, 1e-8f);
    if (lane < K) { rx=__fdiv_rn(rx,den); ry=__fdiv_rn(ry,den); rz=__fdiv_rn(rz,den); }
    else { rx=ry=rz=0.f; }
    float c00=__fmul_rn(rx,rx), c01=__fmul_rn(rx,ry), c02=__fmul_rn(rx,rz);
    float c11=__fmul_rn(ry,ry), c12=__fmul_rn(ry,rz), c22=__fmul_rn(rz,rz);
#pragma unroll
    for (int off = 16; off > 0; off >>= 1) {
        c00=__fadd_rn(c00,__shfl_xor_sync(0xffffffff,c00,off));
        c01=__fadd_rn(c01,__shfl_xor_sync(0xffffffff,c01,off));
        c02=__fadd_rn(c02,__shfl_xor_sync(0xffffffff,c02,off));
        c11=__fadd_rn(c11,__shfl_xor_sync(0xffffffff,c11,off));
        c12=__fadd_rn(c12,__shfl_xor_sync(0xffffffff,c12,off));
        c22=__fadd_rn(c22,__shfl_xor_sync(0xffffffff,c22,off));
    }
    if (lane == 0) {
        float fk=(float)K;
        g_cov[q*6+0]=__fdiv_rn(c00,fk); g_cov[q*6+1]=__fdiv_rn(c01,fk);
        g_cov[q*6+2]=__fdiv_rn(c02,fk); g_cov[q*6+3]=__fdiv_rn(c11,fk);
        g_cov[q*6+4]=__fdiv_rn(c12,fk); g_cov[q*6+5]=__fdiv_rn(c22,fk);
    }
}

// Fused eigh + phi + t-contraction. Block (128) per query.
// t[q,b,c] = (sum_k phi[k,b] * nf[idx[k],c]) / K
__global__ __launch_bounds__(128) void k_tker(int K, int C, const float* __restrict__ nf,
                                              float* __restrict__ tout) {
    __shared__ int   sidx[KMAX];
    __shared__ float sV[9];
    __shared__ float sphi[KMAX*45];
    __shared__ __align__(16) float snf[KMAX*256];
    int q = blockIdx.x, tid = threadIdx.x;
    if (tid < K) sidx[tid] = g_idx[q*KMAX+tid];
    __syncthreads();
    if (tid == 0) {
        // eigh on this query's covariance (same arithmetic as R14 k_eigh)
        float V[3][3];
        eigh3(g_cov[q*6+0], g_cov[q*6+1], g_cov[q*6+3],
              g_cov[q*6+2], g_cov[q*6+4], g_cov[q*6+5], V);
#pragma unroll
        for (int r = 0; r < 3; r++)
#pragma unroll
            for (int c = 0; c < 3; c++) sV[r*3+c] = V[r][c];
    }
    // gather neighbor features (float4, coalesced within rows); overlaps eigh
    {
        int C4 = C >> 2, KC4 = K * C4;
        float4* snf4 = (float4*)snf;
        for (int e = tid; e < KC4; e += 128) {
            int kk = e / C4, c4 = e - kk * C4;
            snf4[kk * C4 + c4] =
                reinterpret_cast<const float4*>(nf + (size_t)sidx[kk] * C)[c4];
        }
    }
    __syncthreads();
    // phi: warp 0, identical arithmetic to R14 k_phi
    if (tid < 32) {
        int lane = tid;
        float4 qp = g_pts[q];
        float rx=0, ry=0, rz=0, nrm=0;
        if (lane < K) {
            float4 p = g_pts[sidx[lane]];
            rx = __fsub_rn(p.x, qp.x);
            ry = __fsub_rn(p.y, qp.y);
            rz = __fsub_rn(p.z, qp.z);
            nrm = __fsqrt_rn(__fadd_rn(__fadd_rn(__fmul_rn(rx,rx),__fmul_rn(ry,ry)),
                                       __fmul_rn(rz,rz)));
        }
        float mx = nrm;
#pragma unroll
        for (int off = 16; off > 0; off >>= 1)
            mx = fmaxf(mx, __shfl_xor_sync(0xffffffff, mx, off));
        float den = __fadd_rn(mx, 1e-8f);
        if (lane < K) {
            rx=__fdiv_rn(rx,den); ry=__fdiv_rn(ry,den); rz=__fdiv_rn(rz,den);
            float v00=sV[0], v01=sV[1], v02=sV[2];
            float v10=sV[3], v11=sV[4], v12=sV[5];
            float v20=sV[6], v21=sV[7], v22=sV[8];
            float X=__fmaf_rn(rz,v20,__fmaf_rn(ry,v10,__fmul_rn(rx,v00)));
            float Y=__fmaf_rn(rz,v21,__fmaf_rn(ry,v11,__fmul_rn(rx,v01)));
            float Z=__fmaf_rn(rz,v22,__fmaf_rn(ry,v12,__fmul_rn(rx,v02)));
            float px[5], py[3], pz[3];
            px[0]=1.f; px[1]=X; px[2]=__fmul_rn(X,X);
            px[3]=__fmul_rn(px[2],X); px[4]=__fmul_rn(px[3],X);
            py[0]=1.f; py[1]=Y; py[2]=__fmul_rn(Y,Y);
            pz[0]=1.f; pz[1]=Z; pz[2]=__fmul_rn(Z,Z);
            float* dst = sphi + lane*45;
#pragma unroll
            for (int n = 0; n < 5; n++)
#pragma unroll
                for (int l = 0; l < 3; l++)
#pragma unroll
                    for (int m = 0; m < 3; m++)
                        dst[n*9+l*3+m] = __fmul_rn(__fmul_rn(px[n],py[l]),pz[m]);
        }
    }
    __syncthreads();
    int E = 45*C; float fk = (float)K;
    for (int e = tid; e < E; e += 128) {
        int b = e / C, c = e - b*C;
        float acc = 0.f;
        for (int kk = 0; kk < K; kk++)
            acc = __fmaf_rn(sphi[kk*45+b], snf[kk*C+c], acc);
        tout[q*E+e] = __fdiv_rn(acc, fk);
    }
}

// plain GEMM: out = relu?(X@W + bias). N%64==0
__global__ __launch_bounds__(128) void k_gemm(int M, int N, int K,
                                              const float* __restrict__ X,
                                              const float* __restrict__ W,
                                              const float* __restrict__ bias,
                                              float* __restrict__ out, int relu) {
    __shared__ float Xs[16][33];
    __shared__ __align__(16) float Ws[32][64];
    int m0 = blockIdx.x*16, n0 = blockIdx.y*64;
    int tid = threadIdx.x, tn = tid & 15, tm = tid >> 4;
    float acc[2][4] = {};
    for (int k0 = 0; k0 < K; k0 += 32) {
#pragma unroll
        for (int j = 0; j < 4; j++) {
            int id = tid*4+j, r = id>>5, c = id&31;
            float v = 0.f;
            if (m0+r < M && k0+c < K) v = X[(m0+r)*K + k0+c];
            Xs[r][c] = v;
        }
#pragma unroll
        for (int j = 0; j < 16; j++) {
            int id = tid + j*128, r = id>>6, c = id&63;
            float v = 0.f;
            if (k0+r < K) v = W[(k0+r)*N + n0+c];
            Ws[r][c] = v;
        }
        __syncthreads();
#pragma unroll
        for (int kk = 0; kk < 32; kk++) {
            float a0 = Xs[tm*2][kk], a1 = Xs[tm*2+1][kk];
            float4 b = *(const float4*)&Ws[kk][tn*4];
            acc[0][0]=__fmaf_rn(a0,b.x,acc[0][0]); acc[0][1]=__fmaf_rn(a0,b.y,acc[0][1]);
            acc[0][2]=__fmaf_rn(a0,b.z,acc[0][2]); acc[0][3]=__fmaf_rn(a0,b.w,acc[0][3]);
            acc[1][0]=__fmaf_rn(a1,b.x,acc[1][0]); acc[1][1]=__fmaf_rn(a1,b.y,acc[1][1]);
            acc[1][2]=__fmaf_rn(a1,b.z,acc[1][2]); acc[1][3]=__fmaf_rn(a1,b.w,acc[1][3]);
        }
        __syncthreads();
    }
#pragma unroll
    for (int i = 0; i < 2; i++) {
        int m = m0 + tm*2 + i;
        if (m < M)
#pragma unroll
            for (int j = 0; j < 4; j++) {
                int n = n0 + tn*4 + j;
                float y = acc[i][j];
                if (bias) y = __fadd_rn(y, bias[n]);
                if (relu) y = fmaxf(y, 0.f);
                out[m*N+n] = y;
            }
    }
}

// split-K GEMM partials
__global__ __launch_bounds__(128) void k_gemm_sk(int M, int N, int K, int Kc,
                                                 const float* __restrict__ X,
                                                 const float* __restrict__ W,
                                                 float* __restrict__ part) {
    __shared__ float Xs[16][33];
    __shared__ __align__(16) float Ws[32][64];
    int m0 = blockIdx.x*16, n0 = blockIdx.y*64, z = blockIdx.z;
    int kbeg = z * Kc, kend = min(K, kbeg + Kc);
    int tid = threadIdx.x, tn = tid & 15, tm = tid >> 4;
    float acc[2][4] = {};
    for (int k0 = kbeg; k0 < kend; k0 += 32) {
#pragma unroll
        for (int j = 0; j < 4; j++) {
            int id = tid*4+j, r = id>>5, c = id&31;
            float v = 0.f;
            if (m0+r < M && k0+c < kend) v = X[(m0+r)*K + k0+c];
            Xs[r][c] = v;
        }
#pragma unroll
        for (int j = 0; j < 16; j++) {
            int id = tid + j*128, r = id>>6, c = id&63;
            float v = 0.f;
            if (k0+r < kend) v = W[(k0+r)*N + n0+c];
            Ws[r][c] = v;
        }
        __syncthreads();
#pragma unroll
        for (int kk = 0; kk < 32; kk++) {
            float a0 = Xs[tm*2][kk], a1 = Xs[tm*2+1][kk];
            float4 b = *(const float4*)&Ws[kk][tn*4];
            acc[0][0]=__fmaf_rn(a0,b.x,acc[0][0]); acc[0][1]=__fmaf_rn(a0,b.y,acc[0][1]);
            acc[0][2]=__fmaf_rn(a0,b.z,acc[0][2]); acc[0][3]=__fmaf_rn(a0,b.w,acc[0][3]);
            acc[1][0]=__fmaf_rn(a1,b.x,acc[1][0]); acc[1][1]=__fmaf_rn(a1,b.y,acc[1][1]);
            acc[1][2]=__fmaf_rn(a1,b.z,acc[1][2]); acc[1][3]=__fmaf_rn(a1,b.w,acc[1][3]);
        }
        __syncthreads();
    }
    float* dst = part + (size_t)z * M * N;
#pragma unroll
    for (int i = 0; i < 2; i++) {
        int m = m0 + tm*2 + i;
        if (m < M)
#pragma unroll
            for (int j = 0; j < 4; j++) {
                int n = n0 + tn*4 + j;
                dst[m*N+n] = acc[i][j];
            }
    }
}

// reduce partials + bias + relu (standalone, for non-residual layers)
__global__ void k_reduce(int MN, int N, int S, const float* __restrict__ part,
                         const float* __restrict__ bias, float* __restrict__ out) {
    int i = blockIdx.x*256 + threadIdx.x;
    if (i >= MN) return;
    float acc = part[i];
    for (int z = 1; z < S; z++) acc = __fadd_rn(acc, part[(size_t)z*MN + i]);
    acc = __fadd_rn(acc, bias[i % N]);
    out[i] = fmaxf(acc, 0.f);
}

// residual GEMM fused with split-K reduce:
// out = relu( relu(sum_z part + bias2) + X@W )
__global__ __launch_bounds__(128) void k_gemm_res(int M, int N, int K,
                                                  const float* __restrict__ X,
                                                  const float* __restrict__ W,
                                                  const float* __restrict__ part, int S,
                                                  const float* __restrict__ bias2,
                                                  float* __restrict__ out) {
    __shared__ float Xs[16][33];
    __shared__ __align__(16) float Ws[32][64];
    int m0 = blockIdx.x*16, n0 = blockIdx.y*64;
    int tid = threadIdx.x, tn = tid & 15, tm = tid >> 4;
    int MN = M * N;
    float acc[2][4] = {};
    for (int k0 = 0; k0 < K; k0 += 32) {
#pragma unroll
        for (int j = 0; j < 4; j++) {
            int id = tid*4+j, r = id>>5, c = id&31;
            float v = 0.f;
            if (m0+r < M && k0+c < K) v = X[(m0+r)*K + k0+c];
            Xs[r][c] = v;
        }
#pragma unroll
        for (int j = 0; j < 16; j++) {
            int id = tid + j*128, r = id>>6, c = id&63;
            float v = 0.f;
            if (k0+r < K) v = W[(k0+r)*N + n0+c];
            Ws[r][c] = v;
        }
        __syncthreads();
#pragma unroll
        for (int kk = 0; kk < 32; kk++) {
            float a0 = Xs[tm*2][kk], a1 = Xs[tm*2+1][kk];
            float4 b = *(const float4*)&Ws[kk][tn*4];
            acc[0][0]=__fmaf_rn(a0,b.x,acc[0][0]); acc[0][1]=__fmaf_rn(a0,b.y,acc[0][1]);
            acc[0][2]=__fmaf_rn(a0,b.z,acc[0][2]); acc[0][3]=__fmaf_rn(a0,b.w,acc[0][3]);
            acc[1][0]=__fmaf_rn(a1,b.x,acc[1][0]); acc[1][1]=__fmaf_rn(a1,b.y,acc[1][1]);
            acc[1][2]=__fmaf_rn(a1,b.z,acc[1][2]); acc[1][3]=__fmaf_rn(a1,b.w,acc[1][3]);
        }
        __syncthreads();
    }
#pragma unroll
    for (int i = 0; i < 2; i++) {
        int m = m0 + tm*2 + i;
        if (m < M)
#pragma unroll
            for (int j = 0; j < 4; j++) {
                int n = n0 + tn*4 + j;
                int i0 = m*N+n;
                float x = part[i0];
                for (int z = 1; z < S; z++) x = __fadd_rn(x, part[(size_t)z*MN + i0]);
                x = __fadd_rn(x, bias2[n]);
                x = fmaxf(x, 0.f);                       // x = relu(t@W + b)
                out[i0] = fmaxf(__fadd_rn(x, acc[i][j]), 0.f);  // relu(x + res)
            }
    }
}

__global__ __launch_bounds__(128) void k_head(const float* __restrict__ hw,
                                              const float* __restrict__ hb,
                                              float* __restrict__ out) {
    __shared__ float red[128];
    int tid = threadIdx.x;
    float acc = 0.f;
    for (int i = tid; i < 512; i += 128)
        acc = __fmaf_rn(g_f4[i], hw[i], acc);
    red[tid] = acc;
    __syncthreads();
    for (int s = 64; s > 0; s >>= 1) {
        if (tid < s) red[tid] = __fadd_rn(red[tid], red[tid+s]);
        __syncthreads();
    }
    if (tid == 0) out[0] = __fadd_rn(red[0], hb[0]);
}

extern "C" void kernel_launch(void* const* d_in, const int* in_sizes, int n_in,
                              void* d_out, int out_size) {
    const float* pos  = (const float*)d_in[0];
    const float* chan = (const float*)d_in[1];
    const float* w[7]; const float* b[7];
    for (int li = 0; li < 7; li++) { w[li] = (const float*)d_in[2+2*li]; b[li] = (const float*)d_in[3+2*li]; }
    const float* p1 = (const float*)d_in[16];
    const float* p2 = (const float*)d_in[17];
    const float* p3 = (const float*)d_in[18];
    const float* p4 = (const float*)d_in[19];
    const float* hw = (const float*)d_in[20];
    const float* hb = (const float*)d_in[21];
    float* out = (float*)d_out;

    void* pv;
    cudaGetSymbolAddress(&pv, g_t);    float* tp  = (float*)pv;
    cudaGetSymbolAddress(&pv, g_xa);   float* xa  = (float*)pv;
    cudaGetSymbolAddress(&pv, g_f1);   float* f1  = (float*)pv;
    cudaGetSymbolAddress(&pv, g_f2);   float* f2  = (float*)pv;
    cudaGetSymbolAddress(&pv, g_f3);   float* f3  = (float*)pv;
    cudaGetSymbolAddress(&pv, g_f4);   float* f4  = (float*)pv;
    cudaGetSymbolAddress(&pv, g_part); float* pp  = (float*)pv;

    k_prep<<<(NPTS+255)/256, 256>>>(pos, NPTS);

    // L1: Q=2435 S=32768 k=16 Cin=4 -> 64
    k_knn_cov<<<(2435+7)/8, 256>>>(2435, NPTS, 16);
    k_tker<<<2435, 128>>>(16, 4, chan, tp);
    k_gemm<<<dim3((2435+15)/16, 1), 128>>>(2435, 64, 180, tp, w[0], b[0], xa, 1);

    // L2: Q=2435 S=2435 k=16 Cin=64 -> 64 ; f1 = relu(relu(t@W2+b2) + chan@p1)
    k_knn_cov<<<(2435+7)/8, 256>>>(2435, 2435, 16);
    k_tker<<<2435, 128>>>(16, 64, xa, tp);
    k_gemm_sk<<<dim3((2435+15)/16, 1, 4), 128>>>(2435, 64, 2880, 720, tp, w[1], pp);
    k_gemm_res<<<dim3((2435+15)/16, 1), 128>>>(2435, 64, 4, chan, p1, pp, 4, b[1], f1);

    // L3: Q=181 S=2435 — kNN/cov = prefix of L2's (bit-identical), reuse rows 0..180
    k_tker<<<181, 128>>>(16, 64, f1, tp);
    k_gemm_sk<<<dim3((181+15)/16, 2, 8), 128>>>(181, 128, 2880, 360, tp, w[2], pp);
    k_reduce<<<(181*128+255)/256, 256>>>(181*128, 128, 8, pp, b[2], xa);

    // L4: Q=181 S=181 ; f2 = relu(relu(t@W4+b4) + f1[:181]@p2)
    k_knn_cov<<<(181+7)/8, 256>>>(181, 181, 16);
    k_tker<<<181, 128>>>(16, 128, xa, tp);
    k_gemm_sk<<<dim3((181+15)/16, 2, 8), 128>>>(181, 128, 5760, 720, tp, w[3], pp);
    k_gemm_res<<<dim3((181+15)/16, 2), 128>>>(181, 128, 64, f1, p2, pp, 8, b[3], f2);

    // L5: Q=13 S=181 — reuse prefix of L4's kNN/cov
    k_tker<<<13, 128>>>(16, 128, f2, tp);
    k_gemm_sk<<<dim3(1, 4, 16), 128>>>(13, 256, 5760, 360, tp, w[4], pp);
    k_reduce<<<(13*256+255)/256, 256>>>(13*256, 256, 16, pp, b[4], xa);

    // L6: Q=13 S=13 k=13 ; f3 = relu(relu(t@W6+b6) + f2[:13]@p3)
    k_knn_cov<<<2, 256>>>(13, 13, 13);
    k_tker<<<13, 128>>>(13, 256, xa, tp);
    k_gemm_sk<<<dim3(1, 4, 32), 128>>>(13, 256, 11520, 360, tp, w[5], pp);
    k_gemm_res<<<dim3(1, 4), 128>>>(13, 256, 128, f2, p3, pp, 32, b[5], f3);

    // L7: Q=1 S=13 k=13 — reuse prefix of L6's kNN/cov
    k_tker<<<1, 128>>>(13, 256, f3, tp);
    k_gemm_sk<<<dim3(1, 8, 32), 128>>>(1, 512, 11520, 360, tp, w[6], pp);
    k_gemm_res<<<dim3(1, 8), 128>>>(1, 512, 256, f3, p4, pp, 32, b[6], f4);

    k_head<<<1, 128>>>(hw, hb, out);
}

// round 16
// speedup vs baseline: 3.5501x; 1.6734x over previous
#include <cuda_runtime.h>
#include <cstdint>

#define KMAX 16
#define NPTS 32768
#define N1 2435

__device__ float4 g_pts[NPTS];
__device__ int    g_idx[N1 * KMAX];
__device__ float  g_cov[N1 * 6];
__device__ float  g_t[N1 * 45 * 64];
__device__ float  g_xa[N1 * 64];
__device__ float  g_f1[N1 * 64];
__device__ float  g_f2[181 * 128];
__device__ float  g_f3[13 * 256];
__device__ float  g_f4[512];
__device__ float  g_part[4 * N1 * 64];

__device__ __forceinline__ bool lexless(float d1, int i1, float d2, int i2) {
    return (d1 < d2) || (d1 == d2 && i1 < i2);
}
#define F_INF __int_as_float(0x7f800000)

// ---------------------------------------------------------------------------
// LAPACK-faithful 3x3 eigh (verified R13 — DO NOT MODIFY)
// ---------------------------------------------------------------------------
__device__ __forceinline__ float slapy2(float x, float y) {
    float xa = fabsf(x), ya = fabsf(y);
    float w = fmaxf(xa, ya), z = fminf(xa, ya);
    if (z == 0.f) return w;
    float q = __fdiv_rn(z, w);
    return __fmul_rn(w, __fsqrt_rn(__fadd_rn(1.f, __fmul_rn(q, q))));
}

__device__ void slaev2(float a, float b, float c,
                       float* rt1, float* rt2, float* cs1, float* sn1) {
    float sm = __fadd_rn(a, c), df = __fsub_rn(a, c), adf = fabsf(df);
    float tb = __fadd_rn(b, b), ab = fabsf(tb);
    float acmx, acmn;
    if (fabsf(a) > fabsf(c)) { acmx = a; acmn = c; } else { acmx = c; acmn = a; }
    float rt;
    if (adf > ab) {
        float q = __fdiv_rn(ab, adf);
        rt = __fmul_rn(adf, __fsqrt_rn(__fadd_rn(1.f, __fmul_rn(q, q))));
    } else if (adf < ab) {
        float q = __fdiv_rn(adf, ab);
        rt = __fmul_rn(ab, __fsqrt_rn(__fadd_rn(1.f, __fmul_rn(q, q))));
    } else {
        rt = __fmul_rn(ab, __fsqrt_rn(2.f));
    }
    int sgn1;
    if (sm < 0.f) {
        *rt1 = __fmul_rn(0.5f, __fsub_rn(sm, rt)); sgn1 = -1;
        *rt2 = __fsub_rn(__fmul_rn(__fdiv_rn(acmx, *rt1), acmn),
                         __fmul_rn(__fdiv_rn(b, *rt1), b));
    } else if (sm > 0.f) {
        *rt1 = __fmul_rn(0.5f, __fadd_rn(sm, rt)); sgn1 = 1;
        *rt2 = __fsub_rn(__fmul_rn(__fdiv_rn(acmx, *rt1), acmn),
                         __fmul_rn(__fdiv_rn(b, *rt1), b));
    } else {
        *rt1 = __fmul_rn(0.5f, rt); *rt2 = __fmul_rn(-0.5f, rt); sgn1 = 1;
    }
    float cs; int sgn2;
    if (df >= 0.f) { cs = __fadd_rn(df, rt); sgn2 = 1; }
    else           { cs = __fsub_rn(df, rt); sgn2 = -1; }
    float acs = fabsf(cs);
    if (acs > ab) {
        float ct = __fdiv_rn(-tb, cs);
        *sn1 = __fdiv_rn(1.f, __fsqrt_rn(__fadd_rn(1.f, __fmul_rn(ct, ct))));
        *cs1 = __fmul_rn(ct, *sn1);
    } else {
        if (ab == 0.f) { *cs1 = 1.f; *sn1 = 0.f; }
        else {
            float tn = __fdiv_rn(-cs, tb);
            *cs1 = __fdiv_rn(1.f, __fsqrt_rn(__fadd_rn(1.f, __fmul_rn(tn, tn))));
            *sn1 = __fmul_rn(tn, *cs1);
        }
    }
    if (sgn1 == sgn2) { float tn = *cs1; *cs1 = -*sn1; *sn1 = tn; }
}

__device__ __forceinline__ void slartg(float f, float g, float* c, float* s, float* r) {
    if (g == 0.f) { *c = 1.f; *s = 0.f; *r = f; }
    else if (f == 0.f) { *c = 0.f; *s = (g > 0.f ? 1.f : -1.f); *r = fabsf(g); }
    else {
        float d = __fsqrt_rn(__fadd_rn(__fmul_rn(f, f), __fmul_rn(g, g)));
        *c = __fdiv_rn(fabsf(f), d);
        *r = (f > 0.f ? d : -d);
        *s = __fdiv_rn(g, *r);
    }
}

__device__ void ssteqr3(float d[3], float e[2], float Z[3][3]) {
    const float eps = 5.9604645e-8f;
    const float eps2 = eps * eps;
    const float safmin = 1.17549435e-38f;
    const int n = 3, nmaxit = 90;
    int jtot = 0, l1 = 0;
    while (l1 < n) {
        if (l1 > 0) e[l1 - 1] = 0.f;
        int m;
        for (m = l1; m < n - 1; m++) {
            float tst = fabsf(e[m]);
            if (tst == 0.f) break;
            if (tst <= __fmul_rn(__fmul_rn(__fsqrt_rn(fabsf(d[m])),
                                           __fsqrt_rn(fabsf(d[m + 1]))), eps)) {
                e[m] = 0.f; break;
            }
        }
        int l = l1, lend = m;
        l1 = m + 1;
        if (lend == l) continue;
        if (fabsf(d[lend]) < fabsf(d[l])) { int t = l; l = lend; lend = t; }
        if (lend > l) {
            for (;;) {
                int mm = lend;
                for (int i = l; i < lend; i++) {
                    float tst = __fmul_rn(e[i], e[i]);
                    if (tst <= __fadd_rn(__fmul_rn(__fmul_rn(eps2, fabsf(d[i])),
                                                   fabsf(d[i + 1])), safmin)) { mm = i; break; }
                }
                if (mm < lend) e[mm] = 0.f;
                float p = d[l];
                if (mm == l) { d[l] = p; l++; if (l <= lend) continue; break; }
                if (mm == l + 1) {
                    float rt1, rt2, c, s;
                    slaev2(d[l], e[l], d[l + 1], &rt1, &rt2, &c, &s);
                    for (int k = 0; k < 3; k++) {
                        float tmp = Z[k][l + 1];
                        Z[k][l + 1] = __fsub_rn(__fmul_rn(c, tmp), __fmul_rn(s, Z[k][l]));
                        Z[k][l]     = __fadd_rn(__fmul_rn(s, tmp), __fmul_rn(c, Z[k][l]));
                    }
                    d[l] = rt1; d[l + 1] = rt2; e[l] = 0.f;
                    l += 2; if (l <= lend) continue; break;
                }
                if (jtot == nmaxit) break;
                jtot++;
                float g = __fdiv_rn(__fsub_rn(d[l + 1], p), __fmul_rn(2.f, e[l]));
                float r = slapy2(g, 1.f);
                g = __fadd_rn(__fsub_rn(d[mm], p),
                              __fdiv_rn(e[l], __fadd_rn(g, copysignf(r, g))));
                float s = 1.f, c = 1.f;
                p = 0.f;
                float csv[2], snv[2];
                for (int i = mm - 1; i >= l; i--) {
                    float f = __fmul_rn(s, e[i]), b = __fmul_rn(c, e[i]);
                    slartg(g, f, &c, &s, &r);
                    if (i != mm - 1) e[i + 1] = r;
                    g = __fsub_rn(d[i + 1], p);
                    r = __fadd_rn(__fmul_rn(__fsub_rn(d[i], g), s),
                                  __fmul_rn(__fmul_rn(2.f, c), b));
                    p = __fmul_rn(s, r);
                    d[i + 1] = __fadd_rn(g, p);
                    g = __fsub_rn(__fmul_rn(c, r), b);
                    csv[i] = c; snv[i] = -s;
                }
                for (int j = mm - 1; j >= l; j--) {
                    float C = csv[j], S = snv[j];
                    for (int k = 0; k < 3; k++) {
                        float tmp = Z[k][j + 1];
                        Z[k][j + 1] = __fsub_rn(__fmul_rn(C, tmp), __fmul_rn(S, Z[k][j]));
                        Z[k][j]     = __fadd_rn(__fmul_rn(S, tmp), __fmul_rn(C, Z[k][j]));
                    }
                }
                d[l] = __fsub_rn(d[l], p); e[l] = g;
            }
        } else {
            for (;;) {
                int mm = lend;
                for (int i = l; i > lend; i--) {
                    float tst = __fmul_rn(e[i - 1], e[i - 1]);
                    if (tst <= __fadd_rn(__fmul_rn(__fmul_rn(eps2, fabsf(d[i])),
                                                   fabsf(d[i - 1])), safmin)) { mm = i; break; }
                }
                if (mm > lend) e[mm - 1] = 0.f;
                float p = d[l];
                if (mm == l) { d[l] = p; l--; if (l >= lend) continue; break; }
                if (mm == l - 1) {
                    float rt1, rt2, c, s;
                    slaev2(d[l - 1], e[l - 1], d[l], &rt1, &rt2, &c, &s);
                    for (int k = 0; k < 3; k++) {
                        float tmp = Z[k][l];
                        Z[k][l]     = __fsub_rn(__fmul_rn(c, tmp), __fmul_rn(s, Z[k][l - 1]));
                        Z[k][l - 1] = __fadd_rn(__fmul_rn(s, tmp), __fmul_rn(c, Z[k][l - 1]));
                    }
                    d[l - 1] = rt1; d[l] = rt2; e[l - 1] = 0.f;
                    l -= 2; if (l >= lend) continue; break;
                }
                if (jtot == nmaxit) break;
                jtot++;
                float g = __fdiv_rn(__fsub_rn(d[l - 1], p), __fmul_rn(2.f, e[l - 1]));
                float r = slapy2(g, 1.f);
                g = __fadd_rn(__fsub_rn(d[mm], p),
                              __fdiv_rn(e[l - 1], __fadd_rn(g, copysignf(r, g))));
                float s = 1.f, c = 1.f;
                p = 0.f;
                float csv[2], snv[2];
                for (int i = mm; i <= l - 1; i++) {
                    float f = __fmul_rn(s, e[i]), b = __fmul_rn(c, e[i]);
                    slartg(g, f, &c, &s, &r);
                    if (i != mm) e[i - 1] = r;
                    g = __fsub_rn(d[i], p);
                    r = __fadd_rn(__fmul_rn(__fsub_rn(d[i + 1], g), s),
                                  __fmul_rn(__fmul_rn(2.f, c), b));
                    p = __fmul_rn(s, r);
                    d[i] = __fadd_rn(g, p);
                    g = __fsub_rn(__fmul_rn(c, r), b);
                    csv[i] = c; snv[i] = s;
                }
                for (int j = mm; j <= l - 1; j++) {
                    float C = csv[j], S = snv[j];
                    for (int k = 0; k < 3; k++) {
                        float tmp = Z[k][j + 1];
                        Z[k][j + 1] = __fsub_rn(__fmul_rn(C, tmp), __fmul_rn(S, Z[k][j]));
                        Z[k][j]     = __fadd_rn(__fmul_rn(S, tmp), __fmul_rn(C, Z[k][j]));
                    }
                }
                d[l] = __fsub_rn(d[l], p); e[l - 1] = g;
            }
        }
    }
    for (int ii = 1; ii < n; ii++) {
        int i = ii - 1, k = i;
        float p = d[i];
        for (int j = ii; j < n; j++) if (d[j] < p) { k = j; p = d[j]; }
        if (k != i) {
            d[k] = d[i]; d[i] = p;
            for (int r2 = 0; r2 < 3; r2++) {
                float t = Z[r2][i]; Z[r2][i] = Z[r2][k]; Z[r2][k] = t;
            }
        }
    }
}

__device__ void eigh3(float a00, float a10, float a11, float a20, float a21, float a22,
                      float V[3][3]) {
    float d[3], e[2], tau, v2;
    d[0] = a00;
    float xnorm = fabsf(a20);
    if (xnorm == 0.f) {
        tau = 0.f; v2 = 0.f;
        e[0] = a10; d[1] = a11; d[2] = a22; e[1] = a21;
    } else {
        float alpha = a10;
        float beta = -copysignf(slapy2(alpha, xnorm), alpha);
        tau = __fdiv_rn(__fsub_rn(beta, alpha), beta);
        v2 = __fmul_rn(a20, __fdiv_rn(1.f, __fsub_rn(alpha, beta)));
        e[0] = beta;
        float w0 = __fmul_rn(tau, __fadd_rn(a11, __fmul_rn(a21, v2)));
        float w1 = __fmul_rn(tau, __fadd_rn(a21, __fmul_rn(a22, v2)));
        float al = __fmul_rn(__fmul_rn(-0.5f, tau), __fadd_rn(w0, __fmul_rn(w1, v2)));
        w0 = __fadd_rn(w0, al);
        w1 = __fadd_rn(w1, __fmul_rn(al, v2));
        d[1] = __fsub_rn(a11, __fmul_rn(2.f, w0));
        e[1] = __fsub_rn(a21, __fadd_rn(__fmul_rn(v2, w0), w1));
        d[2] = __fsub_rn(a22, __fmul_rn(2.f, __fmul_rn(v2, w1)));
    }
    float Z[3][3] = {{1.f,0.f,0.f},{0.f,1.f,0.f},{0.f,0.f,1.f}};
    ssteqr3(d, e, Z);
    if (tau != 0.f) {
        for (int c = 0; c < 3; c++) {
            float dot = __fadd_rn(Z[1][c], __fmul_rn(v2, Z[2][c]));
            float td = __fmul_rn(tau, dot);
            Z[1][c] = __fsub_rn(Z[1][c], td);
            Z[2][c] = __fsub_rn(Z[2][c], __fmul_rn(td, v2));
        }
    }
    for (int r = 0; r < 3; r++)
        for (int c = 0; c < 3; c++) V[r][c] = Z[r][c];
}

// ---------------------------------------------------------------------------
__global__ void k_prep(const float* __restrict__ pos, int n) {
    int i = blockIdx.x * blockDim.x + threadIdx.x;
    if (i < n) {
        float x = pos[3*i], y = pos[3*i+1], z = pos[3*i+2];
        float ss = __fadd_rn(__fadd_rn(__fmul_rn(x,x), __fmul_rn(y,y)), __fmul_rn(z,z));
        g_pts[i] = make_float4(x, y, z, ss);
    }
}

// kNN + cov, with warp-shared gate (16th of lane minima; verified bitonic)
__global__ __launch_bounds__(256) void k_knn_cov(int Q, int S, int K) {
    __shared__ __align__(16) char sbuf[32768];
    float4* stage = (float4*)sbuf;
    float*  sd = (float*)sbuf;
    int*    si = (int*)(sbuf + 16384);
    int w = threadIdx.x >> 5, lane = threadIdx.x & 31;
    int q = blockIdx.x * 8 + w;
    bool act = (q < Q);
    float qx=0,qy=0,qz=0,qq=0;
    if (act) { float4 p = g_pts[q]; qx=p.x; qy=p.y; qz=p.z; qq=p.w; }
    float bd[KMAX]; int bi[KMAX];
#pragma unroll
    for (int j = 0; j < KMAX; j++) { bd[j]=F_INF; bi[j]=0x7FFFFFFF; }
    float Gd = F_INF; int Gi = 0x7FFFFFFF;   // safe upper bound on true 16th
    for (int t0 = 0; t0 < S; t0 += 1024) {
        int cnt = min(1024, S - t0);
        __syncthreads();
        for (int i = threadIdx.x; i < cnt; i += 256) stage[i] = g_pts[t0 + i];
        __syncthreads();
        if (act) {
            for (int i = lane; i < cnt; i += 32) {
                float4 p = stage[i]; int s = t0 + i;
                float G = __fadd_rn(__fadd_rn(__fmul_rn(qx,p.x), __fmul_rn(qy,p.y)), __fmul_rn(qz,p.z));
                float d = __fsub_rn(__fadd_rn(qq, p.w), __fmul_rn(2.0f, G));
                if (lexless(d, s, Gd, Gi) && lexless(d, s, bd[KMAX-1], bi[KMAX-1])) {
                    float cd = d; int ci = s;
#pragma unroll
                    for (int j = 0; j < KMAX; j++)
                        if (lexless(cd, ci, bd[j], bi[j])) {
                            float td=bd[j]; int ti=bi[j]; bd[j]=cd; bi[j]=ci; cd=td; ci=ti;
                        }
                }
            }
            // gate refresh: bitonic-sort lane minima, take 16th; verify sorted
            if (t0 + 1024 < S) {
                float v = bd[0]; int vi = bi[0];
#pragma unroll
                for (int k = 2; k <= 32; k <<= 1) {
#pragma unroll
                    for (int j2 = k >> 1; j2 > 0; j2 >>= 1) {
                        float od = __shfl_xor_sync(0xffffffff, v, j2);
                        int   oi = __shfl_xor_sync(0xffffffff, vi, j2);
                        bool wantMin = (((lane & j2) == 0) == ((lane & k) == 0));
                        bool less = lexless(od, oi, v, vi);
                        if (wantMin == less) { v = od; vi = oi; }
                    }
                }
                float vn = __shfl_down_sync(0xffffffff, v, 1);
                int  vin = __shfl_down_sync(0xffffffff, vi, 1);
                bool ok = (lane == 31) || lexless(v, vi, vn, vin);
                if (__all_sync(0xffffffff, ok)) {
                    Gd = __shfl_sync(0xffffffff, v, 15);
                    Gi = __shfl_sync(0xffffffff, vi, 15);
                }
            }
        }
    }
    __syncthreads();
    if (!act) return;
    float* swd = sd + w * 512; int* swi = si + w * 512;
#pragma unroll
    for (int j = 0; j < KMAX; j++) { swd[lane*KMAX+j]=bd[j]; swi[lane*KMAX+j]=bi[j]; }
    __syncwarp();
    int ptr = 0;
    int selidx = 0;
    for (int r = 0; r < K; r++) {
        float d = swd[lane*KMAX+ptr]; int i = swi[lane*KMAX+ptr]; int ln = lane;
#pragma unroll
        for (int off = 16; off > 0; off >>= 1) {
            float d2 = __shfl_xor_sync(0xffffffff, d, off);
            int   i2 = __shfl_xor_sync(0xffffffff, i, off);
            int   l2 = __shfl_xor_sync(0xffffffff, ln, off);
            if (lexless(d2, i2, d, i)) { d=d2; i=i2; ln=l2; }
        }
        if (lane == r) selidx = i;
        if (lane == ln) { g_idx[q*KMAX+r] = i; ptr++; }
        __syncwarp();
    }
    float rx=0, ry=0, rz=0, nrm=0;
    if (lane < K) {
        float4 p = g_pts[selidx];
        rx = __fsub_rn(p.x, qx);
        ry = __fsub_rn(p.y, qy);
        rz = __fsub_rn(p.z, qz);
        nrm = __fsqrt_rn(__fadd_rn(__fadd_rn(__fmul_rn(rx,rx),__fmul_rn(ry,ry)),__fmul_rn(rz,rz)));
    }
    float mx = nrm;
#pragma unroll
    for (int off = 16; off > 0; off >>= 1) mx = fmaxf(mx, __shfl_xor_sync(0xffffffff, mx, off));
    float den = __fadd_rn(mx, 1e-8f);
    if (lane < K) { rx=__fdiv_rn(rx,den); ry=__fdiv_rn(ry,den); rz=__fdiv_rn(rz,den); }
    else { rx=ry=rz=0.f; }
    float c00=__fmul_rn(rx,rx), c01=__fmul_rn(rx,ry), c02=__fmul_rn(rx,rz);
    float c11=__fmul_rn(ry,ry), c12=__fmul_rn(ry,rz), c22=__fmul_rn(rz,rz);
#pragma unroll
    for (int off = 16; off > 0; off >>= 1) {
        c00=__fadd_rn(c00,__shfl_xor_sync(0xffffffff,c00,off));
        c01=__fadd_rn(c01,__shfl_xor_sync(0xffffffff,c01,off));
        c02=__fadd_rn(c02,__shfl_xor_sync(0xffffffff,c02,off));
        c11=__fadd_rn(c11,__shfl_xor_sync(0xffffffff,c11,off));
        c12=__fadd_rn(c12,__shfl_xor_sync(0xffffffff,c12,off));
        c22=__fadd_rn(c22,__shfl_xor_sync(0xffffffff,c22,off));
    }
    if (lane == 0) {
        float fk=(float)K;
        g_cov[q*6+0]=__fdiv_rn(c00,fk); g_cov[q*6+1]=__fdiv_rn(c01,fk);
        g_cov[q*6+2]=__fdiv_rn(c02,fk); g_cov[q*6+3]=__fdiv_rn(c11,fk);
        g_cov[q*6+4]=__fdiv_rn(c12,fk); g_cov[q*6+5]=__fdiv_rn(c22,fk);
    }
}

// Fused eigh + phi + t-contraction. Block (128) per query.
__global__ __launch_bounds__(128) void k_tker(int K, int C, const float* __restrict__ nf,
                                              float* __restrict__ tout) {
    __shared__ int   sidx[KMAX];
    __shared__ float sV[9];
    __shared__ float sphi[KMAX*45];
    __shared__ __align__(16) float snf[KMAX*256];
    int q = blockIdx.x, tid = threadIdx.x;
    if (tid < K) sidx[tid] = g_idx[q*KMAX+tid];
    __syncthreads();
    if (tid == 127) {
        float V[3][3];
        eigh3(g_cov[q*6+0], g_cov[q*6+1], g_cov[q*6+3],
              g_cov[q*6+2], g_cov[q*6+4], g_cov[q*6+5], V);
#pragma unroll
        for (int r = 0; r < 3; r++)
#pragma unroll
            for (int c = 0; c < 3; c++) sV[r*3+c] = V[r][c];
    } else {
        int C4 = C >> 2, KC4 = K * C4;
        float4* snf4 = (float4*)snf;
        for (int e = tid; e < KC4; e += 127) {
            int kk = e / C4, c4 = e - kk * C4;
            snf4[kk * C4 + c4] =
                reinterpret_cast<const float4*>(nf + (size_t)sidx[kk] * C)[c4];
        }
    }
    __syncthreads();
    if (tid < 32) {
        int lane = tid;
        float4 qp = g_pts[q];
        float rx=0, ry=0, rz=0, nrm=0;
        if (lane < K) {
            float4 p = g_pts[sidx[lane]];
            rx = __fsub_rn(p.x, qp.x);
            ry = __fsub_rn(p.y, qp.y);
            rz = __fsub_rn(p.z, qp.z);
            nrm = __fsqrt_rn(__fadd_rn(__fadd_rn(__fmul_rn(rx,rx),__fmul_rn(ry,ry)),
                                       __fmul_rn(rz,rz)));
        }
        float mx = nrm;
#pragma unroll
        for (int off = 16; off > 0; off >>= 1)
            mx = fmaxf(mx, __shfl_xor_sync(0xffffffff, mx, off));
        float den = __fadd_rn(mx, 1e-8f);
        if (lane < K) {
            rx=__fdiv_rn(rx,den); ry=__fdiv_rn(ry,den); rz=__fdiv_rn(rz,den);
            float v00=sV[0], v01=sV[1], v02=sV[2];
            float v10=sV[3], v11=sV[4], v12=sV[5];
            float v20=sV[6], v21=sV[7], v22=sV[8];
            float X=__fmaf_rn(rz,v20,__fmaf_rn(ry,v10,__fmul_rn(rx,v00)));
            float Y=__fmaf_rn(rz,v21,__fmaf_rn(ry,v11,__fmul_rn(rx,v01)));
            float Z=__fmaf_rn(rz,v22,__fmaf_rn(ry,v12,__fmul_rn(rx,v02)));
            float px[5], py[3], pz[3];
            px[0]=1.f; px[1]=X; px[2]=__fmul_rn(X,X);
            px[3]=__fmul_rn(px[2],X); px[4]=__fmul_rn(px[3],X);
            py[0]=1.f; py[1]=Y; py[2]=__fmul_rn(Y,Y);
            pz[0]=1.f; pz[1]=Z; pz[2]=__fmul_rn(Z,Z);
            float* dst = sphi + lane*45;
#pragma unroll
            for (int n = 0; n < 5; n++)
#pragma unroll
                for (int l = 0; l < 3; l++)
#pragma unroll
                    for (int m = 0; m < 3; m++)
                        dst[n*9+l*3+m] = __fmul_rn(__fmul_rn(px[n],py[l]),pz[m]);
        }
    }
    __syncthreads();
    int E = 45*C; float fk = (float)K;
    for (int e = tid; e < E; e += 128) {
        int b = e / C, c = e - b*C;
        float acc = 0.f;
        for (int kk = 0; kk < K; kk++)
            acc = __fmaf_rn(sphi[kk*45+b], snf[kk*C+c], acc);
        tout[q*E+e] = __fdiv_rn(acc, fk);
    }
}

// ---- GEMM machinery: register-staged double buffer ----
#define GEMM_LOAD(kx, kend_)                                            \
    {                                                                   \
        _Pragma("unroll")                                               \
        for (int j = 0; j < 4; j++) {                                   \
            int id = tid*4+j, r = id>>5, c = id&31;                     \
            rx[j] = 0.f;                                                \
            if (m0+r < M && (kx)+c < (kend_)) rx[j] = X[(m0+r)*K + (kx)+c]; \
        }                                                               \
        _Pragma("unroll")                                               \
        for (int j = 0; j < 16; j++) {                                  \
            int id = tid + j*128, r = id>>6, c = id&63;                 \
            rw[j] = 0.f;                                                \
            if ((kx)+r < (kend_)) rw[j] = W[((kx)+r)*N + n0+c];         \
        }                                                               \
    }

#define GEMM_BODY(kbeg_, kend_)                                         \
    float rx[4], rw[16];                                                \
    float acc[2][4] = {};                                               \
    GEMM_LOAD(kbeg_, kend_);                                            \
    for (int k0 = (kbeg_); k0 < (kend_); k0 += 32) {                    \
        _Pragma("unroll")                                               \
        for (int j = 0; j < 4; j++) { int id = tid*4+j; Xs[id>>5][id&31] = rx[j]; } \
        _Pragma("unroll")                                               \
        for (int j = 0; j < 16; j++) { int id = tid + j*128; Ws[id>>6][id&63] = rw[j]; } \
        __syncthreads();                                                \
        if (k0 + 32 < (kend_)) GEMM_LOAD(k0 + 32, kend_);               \
        _Pragma("unroll")                                               \
        for (int kk = 0; kk < 32; kk++) {                               \
            float a0 = Xs[tm*2][kk], a1 = Xs[tm*2+1][kk];               \
            float4 b = *(const float4*)&Ws[kk][tn*4];                   \
            acc[0][0]=__fmaf_rn(a0,b.x,acc[0][0]); acc[0][1]=__fmaf_rn(a0,b.y,acc[0][1]); \
            acc[0][2]=__fmaf_rn(a0,b.z,acc[0][2]); acc[0][3]=__fmaf_rn(a0,b.w,acc[0][3]); \
            acc[1][0]=__fmaf_rn(a1,b.x,acc[1][0]); acc[1][1]=__fmaf_rn(a1,b.y,acc[1][1]); \
            acc[1][2]=__fmaf_rn(a1,b.z,acc[1][2]); acc[1][3]=__fmaf_rn(a1,b.w,acc[1][3]); \
        }                                                               \
        __syncthreads();                                                \
    }

// plain GEMM: out = relu?(X@W + bias). N%64==0
__global__ __launch_bounds__(128) void k_gemm(int M, int N, int K,
                                              const float* __restrict__ X,
                                              const float* __restrict__ W,
                                              const float* __restrict__ bias,
                                              float* __restrict__ out, int relu) {
    __shared__ float Xs[16][33];
    __shared__ __align__(16) float Ws[32][64];
    int m0 = blockIdx.x*16, n0 = blockIdx.y*64;
    int tid = threadIdx.x, tn = tid & 15, tm = tid >> 4;
    GEMM_BODY(0, K);
#pragma unroll
    for (int i = 0; i < 2; i++) {
        int m = m0 + tm*2 + i;
        if (m < M)
#pragma unroll
            for (int j = 0; j < 4; j++) {
                int n = n0 + tn*4 + j;
                float y = acc[i][j];
                if (bias) y = __fadd_rn(y, bias[n]);
                if (relu) y = fmaxf(y, 0.f);
                out[m*N+n] = y;
            }
    }
}

// split-K GEMM partials
__global__ __launch_bounds__(128) void k_gemm_sk(int M, int N, int K, int Kc,
                                                 const float* __restrict__ X,
                                                 const float* __restrict__ W,
                                                 float* __restrict__ part) {
    __shared__ float Xs[16][33];
    __shared__ __align__(16) float Ws[32][64];
    int m0 = blockIdx.x*16, n0 = blockIdx.y*64, z = blockIdx.z;
    int kbeg = z * Kc, kend = min(K, kbeg + Kc);
    int tid = threadIdx.x, tn = tid & 15, tm = tid >> 4;
    GEMM_BODY(kbeg, kend);
    float* dst = part + (size_t)z * M * N;
#pragma unroll
    for (int i = 0; i < 2; i++) {
        int m = m0 + tm*2 + i;
        if (m < M)
#pragma unroll
            for (int j = 0; j < 4; j++) {
                int n = n0 + tn*4 + j;
                dst[m*N+n] = acc[i][j];
            }
    }
}

// reduce partials + bias + relu
__global__ void k_reduce(int MN, int N, int S, const float* __restrict__ part,
                         const float* __restrict__ bias, float* __restrict__ out) {
    int i = blockIdx.x*256 + threadIdx.x;
    if (i >= MN) return;
    float acc = part[i];
    for (int z = 1; z < S; z++) acc = __fadd_rn(acc, part[(size_t)z*MN + i]);
    acc = __fadd_rn(acc, bias[i % N]);
    out[i] = fmaxf(acc, 0.f);
}

// residual GEMM fused with split-K reduce: out = relu(relu(sum part + b2) + X@W)
__global__ __launch_bounds__(128) void k_gemm_res(int M, int N, int K,
                                                  const float* __restrict__ X,
                                                  const float* __restrict__ W,
                                                  const float* __restrict__ part, int S,
                                                  const float* __restrict__ bias2,
                                                  float* __restrict__ out) {
    __shared__ float Xs[16][33];
    __shared__ __align__(16) float Ws[32][64];
    int m0 = blockIdx.x*16, n0 = blockIdx.y*64;
    int tid = threadIdx.x, tn = tid & 15, tm = tid >> 4;
    int MN = M * N;
    GEMM_BODY(0, K);
#pragma unroll
    for (int i = 0; i < 2; i++) {
        int m = m0 + tm*2 + i;
        if (m < M)
#pragma unroll
            for (int j = 0; j < 4; j++) {
                int n = n0 + tn*4 + j;
                int i0 = m*N+n;
                float x = part[i0];
                for (int z = 1; z < S; z++) x = __fadd_rn(x, part[(size_t)z*MN + i0]);
                x = __fadd_rn(x, bias2[n]);
                x = fmaxf(x, 0.f);
                out[i0] = fmaxf(__fadd_rn(x, acc[i][j]), 0.f);
            }
    }
}

__global__ __launch_bounds__(128) void k_head(const float* __restrict__ hw,
                                              const float* __restrict__ hb,
                                              float* __restrict__ out) {
    __shared__ float red[128];
    int tid = threadIdx.x;
    float acc = 0.f;
    for (int i = tid; i < 512; i += 128)
        acc = __fmaf_rn(g_f4[i], hw[i], acc);
    red[tid] = acc;
    __syncthreads();
    for (int s = 64; s > 0; s >>= 1) {
        if (tid < s) red[tid] = __fadd_rn(red[tid], red[tid+s]);
        __syncthreads();
    }
    if (tid == 0) out[0] = __fadd_rn(red[0], hb[0]);
}

extern "C" void kernel_launch(void* const* d_in, const int* in_sizes, int n_in,
                              void* d_out, int out_size) {
    const float* pos  = (const float*)d_in[0];
    const float* chan = (const float*)d_in[1];
    const float* w[7]; const float* b[7];
    for (int li = 0; li < 7; li++) { w[li] = (const float*)d_in[2+2*li]; b[li] = (const float*)d_in[3+2*li]; }
    const float* p1 = (const float*)d_in[16];
    const float* p2 = (const float*)d_in[17];
    const float* p3 = (const float*)d_in[18];
    const float* p4 = (const float*)d_in[19];
    const float* hw = (const float*)d_in[20];
    const float* hb = (const float*)d_in[21];
    float* out = (float*)d_out;

    void* pv;
    cudaGetSymbolAddress(&pv, g_t);    float* tp  = (float*)pv;
    cudaGetSymbolAddress(&pv, g_xa);   float* xa  = (float*)pv;
    cudaGetSymbolAddress(&pv, g_f1);   float* f1  = (float*)pv;
    cudaGetSymbolAddress(&pv, g_f2);   float* f2  = (float*)pv;
    cudaGetSymbolAddress(&pv, g_f3);   float* f3  = (float*)pv;
    cudaGetSymbolAddress(&pv, g_f4);   float* f4  = (float*)pv;
    cudaGetSymbolAddress(&pv, g_part); float* pp  = (float*)pv;

    k_prep<<<(NPTS+255)/256, 256>>>(pos, NPTS);

    // L1
    k_knn_cov<<<(2435+7)/8, 256>>>(2435, NPTS, 16);
    k_tker<<<2435, 128>>>(16, 4, chan, tp);
    k_gemm<<<dim3((2435+15)/16, 1), 128>>>(2435, 64, 180, tp, w[0], b[0], xa, 1);

    // L2
    k_knn_cov<<<(2435+7)/8, 256>>>(2435, 2435, 16);
    k_tker<<<2435, 128>>>(16, 64, xa, tp);
    k_gemm_sk<<<dim3((2435+15)/16, 1, 4), 128>>>(2435, 64, 2880, 720, tp, w[1], pp);
    k_gemm_res<<<dim3((2435+15)/16, 1), 128>>>(2435, 64, 4, chan, p1, pp, 4, b[1], f1);

    // L3 (kNN/cov prefix-reuse of L2)
    k_tker<<<181, 128>>>(16, 64, f1, tp);
    k_gemm_sk<<<dim3((181+15)/16, 2, 8), 128>>>(181, 128, 2880, 360, tp, w[2], pp);
    k_reduce<<<(181*128+255)/256, 256>>>(181*128, 128, 8, pp, b[2], xa);

    // L4
    k_knn_cov<<<(181+7)/8, 256>>>(181, 181, 16);
    k_tker<<<181, 128>>>(16, 128, xa, tp);
    k_gemm_sk<<<dim3((181+15)/16, 2, 8), 128>>>(181, 128, 5760, 720, tp, w[3], pp);
    k_gemm_res<<<dim3((181+15)/16, 2), 128>>>(181, 128, 64, f1, p2, pp, 8, b[3], f2);

    // L5 (prefix-reuse of L4)
    k_tker<<<13, 128>>>(16, 128, f2, tp);
    k_gemm_sk<<<dim3(1, 4, 16), 128>>>(13, 256, 5760, 360, tp, w[4], pp);
    k_reduce<<<(13*256+255)/256, 256>>>(13*256, 256, 16, pp, b[4], xa);

    // L6
    k_knn_cov<<<2, 256>>>(13, 13, 13);
    k_tker<<<13, 128>>>(13, 256, xa, tp);
    k_gemm_sk<<<dim3(1, 4, 32), 128>>>(13, 256, 11520, 360, tp, w[5], pp);
    k_gemm_res<<<dim3(1, 4), 128>>>(13, 256, 128, f2, p3, pp, 32, b[5], f3);

    // L7 (prefix-reuse of L6)
    k_tker<<<1, 128>>>(13, 256, f3, tp);
    k_gemm_sk<<<dim3(1, 8, 32), 128>>>(1, 512, 11520, 360, tp, w[6], pp);
    k_gemm_res<<<dim3(1, 8), 128>>>(1, 512, 256, f3, p4, pp, 32, b[6], f4);

    k_head<<<1, 128>>>(hw, hb, out);
}

// round 17
// speedup vs baseline: 4.0088x; 1.1292x over previous
#include <cuda_runtime.h>
#include <cstdint>

#define KMAX 16
#define NPTS 32768
#define N1 2435

__device__ float4 g_pts[NPTS];
__device__ int    g_idx1[N1 * KMAX];
__device__ float  g_cov1[N1 * 6];
__device__ int    g_idx2[N1 * KMAX];
__device__ float  g_cov2[N1 * 6];
__device__ int    g_idx4[181 * KMAX];
__device__ float  g_cov4[181 * 6];
__device__ int    g_idx6[13 * KMAX];
__device__ float  g_cov6[13 * 6];
__device__ float  g_t[N1 * 45 * 64];
__device__ float  g_xa[N1 * 64];
__device__ float  g_f1[N1 * 64];
__device__ float  g_f2[181 * 128];
__device__ float  g_f3[13 * 256];
__device__ float  g_f4[512];
__device__ float  g_part[4 * N1 * 64];
__device__ int    g_ctr[256];            // zero-init; reset-after-use

__device__ __forceinline__ bool lexless(float d1, int i1, float d2, int i2) {
    return (d1 < d2) || (d1 == d2 && i1 < i2);
}
#define F_INF __int_as_float(0x7f800000)

// ---------------------------------------------------------------------------
// LAPACK-faithful 3x3 eigh (verified R13 — DO NOT MODIFY)
// ---------------------------------------------------------------------------
__device__ __forceinline__ float slapy2(float x, float y) {
    float xa = fabsf(x), ya = fabsf(y);
    float w = fmaxf(xa, ya), z = fminf(xa, ya);
    if (z == 0.f) return w;
    float q = __fdiv_rn(z, w);
    return __fmul_rn(w, __fsqrt_rn(__fadd_rn(1.f, __fmul_rn(q, q))));
}

__device__ void slaev2(float a, float b, float c,
                       float* rt1, float* rt2, float* cs1, float* sn1) {
    float sm = __fadd_rn(a, c), df = __fsub_rn(a, c), adf = fabsf(df);
    float tb = __fadd_rn(b, b), ab = fabsf(tb);
    float acmx, acmn;
    if (fabsf(a) > fabsf(c)) { acmx = a; acmn = c; } else { acmx = c; acmn = a; }
    float rt;
    if (adf > ab) {
        float q = __fdiv_rn(ab, adf);
        rt = __fmul_rn(adf, __fsqrt_rn(__fadd_rn(1.f, __fmul_rn(q, q))));
    } else if (adf < ab) {
        float q = __fdiv_rn(adf, ab);
        rt = __fmul_rn(ab, __fsqrt_rn(__fadd_rn(1.f, __fmul_rn(q, q))));
    } else {
        rt = __fmul_rn(ab, __fsqrt_rn(2.f));
    }
    int sgn1;
    if (sm < 0.f) {
        *rt1 = __fmul_rn(0.5f, __fsub_rn(sm, rt)); sgn1 = -1;
        *rt2 = __fsub_rn(__fmul_rn(__fdiv_rn(acmx, *rt1), acmn),
                         __fmul_rn(__fdiv_rn(b, *rt1), b));
    } else if (sm > 0.f) {
        *rt1 = __fmul_rn(0.5f, __fadd_rn(sm, rt)); sgn1 = 1;
        *rt2 = __fsub_rn(__fmul_rn(__fdiv_rn(acmx, *rt1), acmn),
                         __fmul_rn(__fdiv_rn(b, *rt1), b));
    } else {
        *rt1 = __fmul_rn(0.5f, rt); *rt2 = __fmul_rn(-0.5f, rt); sgn1 = 1;
    }
    float cs; int sgn2;
    if (df >= 0.f) { cs = __fadd_rn(df, rt); sgn2 = 1; }
    else           { cs = __fsub_rn(df, rt); sgn2 = -1; }
    float acs = fabsf(cs);
    if (acs > ab) {
        float ct = __fdiv_rn(-tb, cs);
        *sn1 = __fdiv_rn(1.f, __fsqrt_rn(__fadd_rn(1.f, __fmul_rn(ct, ct))));
        *cs1 = __fmul_rn(ct, *sn1);
    } else {
        if (ab == 0.f) { *cs1 = 1.f; *sn1 = 0.f; }
        else {
            float tn = __fdiv_rn(-cs, tb);
            *cs1 = __fdiv_rn(1.f, __fsqrt_rn(__fadd_rn(1.f, __fmul_rn(tn, tn))));
            *sn1 = __fmul_rn(tn, *cs1);
        }
    }
    if (sgn1 == sgn2) { float tn = *cs1; *cs1 = -*sn1; *sn1 = tn; }
}

__device__ __forceinline__ void slartg(float f, float g, float* c, float* s, float* r) {
    if (g == 0.f) { *c = 1.f; *s = 0.f; *r = f; }
    else if (f == 0.f) { *c = 0.f; *s = (g > 0.f ? 1.f : -1.f); *r = fabsf(g); }
    else {
        float d = __fsqrt_rn(__fadd_rn(__fmul_rn(f, f), __fmul_rn(g, g)));
        *c = __fdiv_rn(fabsf(f), d);
        *r = (f > 0.f ? d : -d);
        *s = __fdiv_rn(g, *r);
    }
}

__device__ void ssteqr3(float d[3], float e[2], float Z[3][3]) {
    const float eps = 5.9604645e-8f;
    const float eps2 = eps * eps;
    const float safmin = 1.17549435e-38f;
    const int n = 3, nmaxit = 90;
    int jtot = 0, l1 = 0;
    while (l1 < n) {
        if (l1 > 0) e[l1 - 1] = 0.f;
        int m;
        for (m = l1; m < n - 1; m++) {
            float tst = fabsf(e[m]);
            if (tst == 0.f) break;
            if (tst <= __fmul_rn(__fmul_rn(__fsqrt_rn(fabsf(d[m])),
                                           __fsqrt_rn(fabsf(d[m + 1]))), eps)) {
                e[m] = 0.f; break;
            }
        }
        int l = l1, lend = m;
        l1 = m + 1;
        if (lend == l) continue;
        if (fabsf(d[lend]) < fabsf(d[l])) { int t = l; l = lend; lend = t; }
        if (lend > l) {
            for (;;) {
                int mm = lend;
                for (int i = l; i < lend; i++) {
                    float tst = __fmul_rn(e[i], e[i]);
                    if (tst <= __fadd_rn(__fmul_rn(__fmul_rn(eps2, fabsf(d[i])),
                                                   fabsf(d[i + 1])), safmin)) { mm = i; break; }
                }
                if (mm < lend) e[mm] = 0.f;
                float p = d[l];
                if (mm == l) { d[l] = p; l++; if (l <= lend) continue; break; }
                if (mm == l + 1) {
                    float rt1, rt2, c, s;
                    slaev2(d[l], e[l], d[l + 1], &rt1, &rt2, &c, &s);
                    for (int k = 0; k < 3; k++) {
                        float tmp = Z[k][l + 1];
                        Z[k][l + 1] = __fsub_rn(__fmul_rn(c, tmp), __fmul_rn(s, Z[k][l]));
                        Z[k][l]     = __fadd_rn(__fmul_rn(s, tmp), __fmul_rn(c, Z[k][l]));
                    }
                    d[l] = rt1; d[l + 1] = rt2; e[l] = 0.f;
                    l += 2; if (l <= lend) continue; break;
                }
                if (jtot == nmaxit) break;
                jtot++;
                float g = __fdiv_rn(__fsub_rn(d[l + 1], p), __fmul_rn(2.f, e[l]));
                float r = slapy2(g, 1.f);
                g = __fadd_rn(__fsub_rn(d[mm], p),
                              __fdiv_rn(e[l], __fadd_rn(g, copysignf(r, g))));
                float s = 1.f, c = 1.f;
                p = 0.f;
                float csv[2], snv[2];
                for (int i = mm - 1; i >= l; i--) {
                    float f = __fmul_rn(s, e[i]), b = __fmul_rn(c, e[i]);
                    slartg(g, f, &c, &s, &r);
                    if (i != mm - 1) e[i + 1] = r;
                    g = __fsub_rn(d[i + 1], p);
                    r = __fadd_rn(__fmul_rn(__fsub_rn(d[i], g), s),
                                  __fmul_rn(__fmul_rn(2.f, c), b));
                    p = __fmul_rn(s, r);
                    d[i + 1] = __fadd_rn(g, p);
                    g = __fsub_rn(__fmul_rn(c, r), b);
                    csv[i] = c; snv[i] = -s;
                }
                for (int j = mm - 1; j >= l; j--) {
                    float C = csv[j], S = snv[j];
                    for (int k = 0; k < 3; k++) {
                        float tmp = Z[k][j + 1];
                        Z[k][j + 1] = __fsub_rn(__fmul_rn(C, tmp), __fmul_rn(S, Z[k][j]));
                        Z[k][j]     = __fadd_rn(__fmul_rn(S, tmp), __fmul_rn(C, Z[k][j]));
                    }
                }
                d[l] = __fsub_rn(d[l], p); e[l] = g;
            }
        } else {
            for (;;) {
                int mm = lend;
                for (int i = l; i > lend; i--) {
                    float tst = __fmul_rn(e[i - 1], e[i - 1]);
                    if (tst <= __fadd_rn(__fmul_rn(__fmul_rn(eps2, fabsf(d[i])),
                                                   fabsf(d[i - 1])), safmin)) { mm = i; break; }
                }
                if (mm > lend) e[mm - 1] = 0.f;
                float p = d[l];
                if (mm == l) { d[l] = p; l--; if (l >= lend) continue; break; }
                if (mm == l - 1) {
                    float rt1, rt2, c, s;
                    slaev2(d[l - 1], e[l - 1], d[l], &rt1, &rt2, &c, &s);
                    for (int k = 0; k < 3; k++) {
                        float tmp = Z[k][l];
                        Z[k][l]     = __fsub_rn(__fmul_rn(c, tmp), __fmul_rn(s, Z[k][l - 1]));
                        Z[k][l - 1] = __fadd_rn(__fmul_rn(s, tmp), __fmul_rn(c, Z[k][l - 1]));
                    }
                    d[l - 1] = rt1; d[l] = rt2; e[l - 1] = 0.f;
                    l -= 2; if (l >= lend) continue; break;
                }
                if (jtot == nmaxit) break;
                jtot++;
                float g = __fdiv_rn(__fsub_rn(d[l - 1], p), __fmul_rn(2.f, e[l - 1]));
                float r = slapy2(g, 1.f);
                g = __fadd_rn(__fsub_rn(d[mm], p),
                              __fdiv_rn(e[l - 1], __fadd_rn(g, copysignf(r, g))));
                float s = 1.f, c = 1.f;
                p = 0.f;
                float csv[2], snv[2];
                for (int i = mm; i <= l - 1; i++) {
                    float f = __fmul_rn(s, e[i]), b = __fmul_rn(c, e[i]);
                    slartg(g, f, &c, &s, &r);
                    if (i != mm) e[i - 1] = r;
                    g = __fsub_rn(d[i], p);
                    r = __fadd_rn(__fmul_rn(__fsub_rn(d[i + 1], g), s),
                                  __fmul_rn(__fmul_rn(2.f, c), b));
                    p = __fmul_rn(s, r);
                    d[i] = __fadd_rn(g, p);
                    g = __fsub_rn(__fmul_rn(c, r), b);
                    csv[i] = c; snv[i] = s;
                }
                for (int j = mm; j <= l - 1; j++) {
                    float C = csv[j], S = snv[j];
                    for (int k = 0; k < 3; k++) {
                        float tmp = Z[k][j + 1];
                        Z[k][j + 1] = __fsub_rn(__fmul_rn(C, tmp), __fmul_rn(S, Z[k][j]));
                        Z[k][j]     = __fadd_rn(__fmul_rn(S, tmp), __fmul_rn(C, Z[k][j]));
                    }
                }
                d[l] = __fsub_rn(d[l], p); e[l - 1] = g;
            }
        }
    }
    for (int ii = 1; ii < n; ii++) {
        int i = ii - 1, k = i;
        float p = d[i];
        for (int j = ii; j < n; j++) if (d[j] < p) { k = j; p = d[j]; }
        if (k != i) {
            d[k] = d[i]; d[i] = p;
            for (int r2 = 0; r2 < 3; r2++) {
                float t = Z[r2][i]; Z[r2][i] = Z[r2][k]; Z[r2][k] = t;
            }
        }
    }
}

__device__ void eigh3(float a00, float a10, float a11, float a20, float a21, float a22,
                      float V[3][3]) {
    float d[3], e[2], tau, v2;
    d[0] = a00;
    float xnorm = fabsf(a20);
    if (xnorm == 0.f) {
        tau = 0.f; v2 = 0.f;
        e[0] = a10; d[1] = a11; d[2] = a22; e[1] = a21;
    } else {
        float alpha = a10;
        float beta = -copysignf(slapy2(alpha, xnorm), alpha);
        tau = __fdiv_rn(__fsub_rn(beta, alpha), beta);
        v2 = __fmul_rn(a20, __fdiv_rn(1.f, __fsub_rn(alpha, beta)));
        e[0] = beta;
        float w0 = __fmul_rn(tau, __fadd_rn(a11, __fmul_rn(a21, v2)));
        float w1 = __fmul_rn(tau, __fadd_rn(a21, __fmul_rn(a22, v2)));
        float al = __fmul_rn(__fmul_rn(-0.5f, tau), __fadd_rn(w0, __fmul_rn(w1, v2)));
        w0 = __fadd_rn(w0, al);
        w1 = __fadd_rn(w1, __fmul_rn(al, v2));
        d[1] = __fsub_rn(a11, __fmul_rn(2.f, w0));
        e[1] = __fsub_rn(a21, __fadd_rn(__fmul_rn(v2, w0), w1));
        d[2] = __fsub_rn(a22, __fmul_rn(2.f, __fmul_rn(v2, w1)));
    }
    float Z[3][3] = {{1.f,0.f,0.f},{0.f,1.f,0.f},{0.f,0.f,1.f}};
    ssteqr3(d, e, Z);
    if (tau != 0.f) {
        for (int c = 0; c < 3; c++) {
            float dot = __fadd_rn(Z[1][c], __fmul_rn(v2, Z[2][c]));
            float td = __fmul_rn(tau, dot);
            Z[1][c] = __fsub_rn(Z[1][c], td);
            Z[2][c] = __fsub_rn(Z[2][c], __fmul_rn(td, v2));
        }
    }
    for (int r = 0; r < 3; r++)
        for (int c = 0; c < 3; c++) V[r][c] = Z[r][c];
}

// ---------------------------------------------------------------------------
__global__ void k_prep(const float* __restrict__ pos, int n) {
    int i = blockIdx.x * blockDim.x + threadIdx.x;
    if (i < n) {
        float x = pos[3*i], y = pos[3*i+1], z = pos[3*i+2];
        float ss = __fadd_rn(__fadd_rn(__fmul_rn(x,x), __fmul_rn(y,y)), __fmul_rn(z,z));
        g_pts[i] = make_float4(x, y, z, ss);
    }
}

// kNN + cov body (warp/query, smem tiles, warp-shared gate, 2-way ILP).
// Selection is exact lexicographic (d, idx) top-K — bit-identical to R15.
__device__ void knn_body(int bid, int Q, int S, int K,
                         int* __restrict__ idxOut, float* __restrict__ covOut,
                         char* sbuf) {
    float4* stage = (float4*)sbuf;
    float*  sd = (float*)sbuf;
    int*    si = (int*)(sbuf + 16384);
    int w = threadIdx.x >> 5, lane = threadIdx.x & 31;
    int q = bid * 8 + w;
    bool act = (q < Q);
    float qx=0,qy=0,qz=0,qq=0;
    if (act) { float4 p = g_pts[q]; qx=p.x; qy=p.y; qz=p.z; qq=p.w; }
    float bd[KMAX]; int bi[KMAX];
#pragma unroll
    for (int j = 0; j < KMAX; j++) { bd[j]=F_INF; bi[j]=0x7FFFFFFF; }
    float Gd = F_INF; int Gi = 0x7FFFFFFF;
    for (int t0 = 0; t0 < S; t0 += 1024) {
        int cnt = min(1024, S - t0);
        __syncthreads();
        for (int i = threadIdx.x; i < cnt; i += 256) stage[i] = g_pts[t0 + i];
        __syncthreads();
        if (act) {
            for (int i = lane; i < cnt; i += 64) {
                float4 pA = stage[i];
                int iB = i + 32;
                bool hasB = (iB < cnt);
                float4 pB = hasB ? stage[iB] : pA;
                float GA = __fadd_rn(__fadd_rn(__fmul_rn(qx,pA.x), __fmul_rn(qy,pA.y)), __fmul_rn(qz,pA.z));
                float GB = __fadd_rn(__fadd_rn(__fmul_rn(qx,pB.x), __fmul_rn(qy,pB.y)), __fmul_rn(qz,pB.z));
                float dA = __fsub_rn(__fadd_rn(qq, pA.w), __fmul_rn(2.0f, GA));
                float dB = __fsub_rn(__fadd_rn(qq, pB.w), __fmul_rn(2.0f, GB));
                int sA = t0 + i, sB = t0 + iB;
                if (lexless(dA, sA, Gd, Gi) && lexless(dA, sA, bd[KMAX-1], bi[KMAX-1])) {
                    float cd = dA; int ci = sA;
#pragma unroll
                    for (int j = 0; j < KMAX; j++)
                        if (lexless(cd, ci, bd[j], bi[j])) {
                            float td=bd[j]; int ti=bi[j]; bd[j]=cd; bi[j]=ci; cd=td; ci=ti;
                        }
                }
                if (hasB && lexless(dB, sB, Gd, Gi) && lexless(dB, sB, bd[KMAX-1], bi[KMAX-1])) {
                    float cd = dB; int ci = sB;
#pragma unroll
                    for (int j = 0; j < KMAX; j++)
                        if (lexless(cd, ci, bd[j], bi[j])) {
                            float td=bd[j]; int ti=bi[j]; bd[j]=cd; bi[j]=ci; cd=td; ci=ti;
                        }
                }
            }
            if (t0 + 1024 < S) {
                float v = bd[0]; int vi = bi[0];
#pragma unroll
                for (int k = 2; k <= 32; k <<= 1) {
#pragma unroll
                    for (int j2 = k >> 1; j2 > 0; j2 >>= 1) {
                        float od = __shfl_xor_sync(0xffffffff, v, j2);
                        int   oi = __shfl_xor_sync(0xffffffff, vi, j2);
                        bool wantMin = (((lane & j2) == 0) == ((lane & k) == 0));
                        bool less = lexless(od, oi, v, vi);
                        if (wantMin == less) { v = od; vi = oi; }
                    }
                }
                float vn = __shfl_down_sync(0xffffffff, v, 1);
                int  vin = __shfl_down_sync(0xffffffff, vi, 1);
                bool ok = (lane == 31) || lexless(v, vi, vn, vin);
                if (__all_sync(0xffffffff, ok)) {
                    Gd = __shfl_sync(0xffffffff, v, 15);
                    Gi = __shfl_sync(0xffffffff, vi, 15);
                }
            }
        }
    }
    __syncthreads();
    if (!act) return;
    float* swd = sd + w * 512; int* swi = si + w * 512;
#pragma unroll
    for (int j = 0; j < KMAX; j++) { swd[lane*KMAX+j]=bd[j]; swi[lane*KMAX+j]=bi[j]; }
    __syncwarp();
    int ptr = 0;
    int selidx = 0;
    for (int r = 0; r < K; r++) {
        float d = swd[lane*KMAX+ptr]; int i = swi[lane*KMAX+ptr]; int ln = lane;
#pragma unroll
        for (int off = 16; off > 0; off >>= 1) {
            float d2 = __shfl_xor_sync(0xffffffff, d, off);
            int   i2 = __shfl_xor_sync(0xffffffff, i, off);
            int   l2 = __shfl_xor_sync(0xffffffff, ln, off);
            if (lexless(d2, i2, d, i)) { d=d2; i=i2; ln=l2; }
        }
        if (lane == r) selidx = i;
        if (lane == ln) { idxOut[q*KMAX+r] = i; ptr++; }
        __syncwarp();
    }
    float rx=0, ry=0, rz=0, nrm=0;
    if (lane < K) {
        float4 p = g_pts[selidx];
        rx = __fsub_rn(p.x, qx);
        ry = __fsub_rn(p.y, qy);
        rz = __fsub_rn(p.z, qz);
        nrm = __fsqrt_rn(__fadd_rn(__fadd_rn(__fmul_rn(rx,rx),__fmul_rn(ry,ry)),__fmul_rn(rz,rz)));
    }
    float mx = nrm;
#pragma unroll
    for (int off = 16; off > 0; off >>= 1) mx = fmaxf(mx, __shfl_xor_sync(0xffffffff, mx, off));
    float den = __fadd_rn(mx, 1e-8f);
    if (lane < K) { rx=__fdiv_rn(rx,den); ry=__fdiv_rn(ry,den); rz=__fdiv_rn(rz,den); }
    else { rx=ry=rz=0.f; }
    float c00=__fmul_rn(rx,rx), c01=__fmul_rn(rx,ry), c02=__fmul_rn(rx,rz);
    float c11=__fmul_rn(ry,ry), c12=__fmul_rn(ry,rz), c22=__fmul_rn(rz,rz);
#pragma unroll
    for (int off = 16; off > 0; off >>= 1) {
        c00=__fadd_rn(c00,__shfl_xor_sync(0xffffffff,c00,off));
        c01=__fadd_rn(c01,__shfl_xor_sync(0xffffffff,c01,off));
        c02=__fadd_rn(c02,__shfl_xor_sync(0xffffffff,c02,off));
        c11=__fadd_rn(c11,__shfl_xor_sync(0xffffffff,c11,off));
        c12=__fadd_rn(c12,__shfl_xor_sync(0xffffffff,c12,off));
        c22=__fadd_rn(c22,__shfl_xor_sync(0xffffffff,c22,off));
    }
    if (lane == 0) {
        float fk=(float)K;
        covOut[q*6+0]=__fdiv_rn(c00,fk); covOut[q*6+1]=__fdiv_rn(c01,fk);
        covOut[q*6+2]=__fdiv_rn(c02,fk); covOut[q*6+3]=__fdiv_rn(c11,fk);
        covOut[q*6+4]=__fdiv_rn(c12,fk); covOut[q*6+5]=__fdiv_rn(c22,fk);
    }
}

// ALL four kNN+cov passes in one kernel (they depend only on g_pts)
__global__ __launch_bounds__(256) void k_mknn() {
    __shared__ __align__(16) char sbuf[32768];
    int b = blockIdx.x;
    if (b < 305)       knn_body(b,       2435, NPTS, 16, g_idx1, g_cov1, sbuf);
    else if (b < 610)  knn_body(b - 305, 2435, 2435, 16, g_idx2, g_cov2, sbuf);
    else if (b < 633)  knn_body(b - 610, 181,  181,  16, g_idx4, g_cov4, sbuf);
    else               knn_body(b - 633, 13,   13,   13, g_idx6, g_cov6, sbuf);
}

// Fused eigh + phi + t-contraction. Block (128) per query.
__global__ __launch_bounds__(128) void k_tker(int K, int C, const float* __restrict__ nf,
                                              float* __restrict__ tout,
                                              const int* __restrict__ idx,
                                              const float* __restrict__ cov) {
    __shared__ int   sidx[KMAX];
    __shared__ float sV[9];
    __shared__ float sphi[KMAX*45];
    __shared__ __align__(16) float snf[KMAX*256];
    int q = blockIdx.x, tid = threadIdx.x;
    if (tid < K) sidx[tid] = idx[q*KMAX+tid];
    __syncthreads();
    if (tid == 127) {
        float V[3][3];
        eigh3(cov[q*6+0], cov[q*6+1], cov[q*6+3],
              cov[q*6+2], cov[q*6+4], cov[q*6+5], V);
#pragma unroll
        for (int r = 0; r < 3; r++)
#pragma unroll
            for (int c = 0; c < 3; c++) sV[r*3+c] = V[r][c];
    } else {
        int C4 = C >> 2, KC4 = K * C4;
        float4* snf4 = (float4*)snf;
        for (int e = tid; e < KC4; e += 127) {
            int kk = e / C4, c4 = e - kk * C4;
            snf4[kk * C4 + c4] =
                reinterpret_cast<const float4*>(nf + (size_t)sidx[kk] * C)[c4];
        }
    }
    __syncthreads();
    if (tid < 32) {
        int lane = tid;
        float4 qp = g_pts[q];
        float rx=0, ry=0, rz=0, nrm=0;
        if (lane < K) {
            float4 p = g_pts[sidx[lane]];
            rx = __fsub_rn(p.x, qp.x);
            ry = __fsub_rn(p.y, qp.y);
            rz = __fsub_rn(p.z, qp.z);
            nrm = __fsqrt_rn(__fadd_rn(__fadd_rn(__fmul_rn(rx,rx),__fmul_rn(ry,ry)),
                                       __fmul_rn(rz,rz)));
        }
        float mx = nrm;
#pragma unroll
        for (int off = 16; off > 0; off >>= 1)
            mx = fmaxf(mx, __shfl_xor_sync(0xffffffff, mx, off));
        float den = __fadd_rn(mx, 1e-8f);
        if (lane < K) {
            rx=__fdiv_rn(rx,den); ry=__fdiv_rn(ry,den); rz=__fdiv_rn(rz,den);
            float v00=sV[0], v01=sV[1], v02=sV[2];
            float v10=sV[3], v11=sV[4], v12=sV[5];
            float v20=sV[6], v21=sV[7], v22=sV[8];
            float X=__fmaf_rn(rz,v20,__fmaf_rn(ry,v10,__fmul_rn(rx,v00)));
            float Y=__fmaf_rn(rz,v21,__fmaf_rn(ry,v11,__fmul_rn(rx,v01)));
            float Z=__fmaf_rn(rz,v22,__fmaf_rn(ry,v12,__fmul_rn(rx,v02)));
            float px[5], py[3], pz[3];
            px[0]=1.f; px[1]=X; px[2]=__fmul_rn(X,X);
            px[3]=__fmul_rn(px[2],X); px[4]=__fmul_rn(px[3],X);
            py[0]=1.f; py[1]=Y; py[2]=__fmul_rn(Y,Y);
            pz[0]=1.f; pz[1]=Z; pz[2]=__fmul_rn(Z,Z);
            float* dst = sphi + lane*45;
#pragma unroll
            for (int n = 0; n < 5; n++)
#pragma unroll
                for (int l = 0; l < 3; l++)
#pragma unroll
                    for (int m = 0; m < 3; m++)
                        dst[n*9+l*3+m] = __fmul_rn(__fmul_rn(px[n],py[l]),pz[m]);
        }
    }
    __syncthreads();
    int E = 45*C; float fk = (float)K;
    for (int e = tid; e < E; e += 128) {
        int b = e / C, c = e - b*C;
        float acc = 0.f;
        for (int kk = 0; kk < K; kk++)
            acc = __fmaf_rn(sphi[kk*45+b], snf[kk*C+c], acc);
        tout[q*E+e] = __fdiv_rn(acc, fk);
    }
}

// ---- GEMM machinery: register-staged double buffer ----
#define GEMM_LOAD(XP, WP, LDX, kx, kend_)                               \
    {                                                                   \
        _Pragma("unroll")                                               \
        for (int j = 0; j < 4; j++) {                                   \
            int id = tid*4+j, r = id>>5, c = id&31;                     \
            rx[j] = 0.f;                                                \
            if (m0+r < M && (kx)+c < (kend_)) rx[j] = (XP)[(m0+r)*(LDX) + (kx)+c]; \
        }                                                               \
        _Pragma("unroll")                                               \
        for (int j = 0; j < 16; j++) {                                  \
            int id = tid + j*128, r = id>>6, c = id&63;                 \
            rw[j] = 0.f;                                                \
            if ((kx)+r < (kend_)) rw[j] = (WP)[((kx)+r)*N + n0+c];      \
        }                                                               \
    }

#define GEMM_BODY(XP, WP, LDX, kbeg_, kend_)                            \
    float rx[4], rw[16];                                                \
    float acc[2][4] = {};                                               \
    GEMM_LOAD(XP, WP, LDX, kbeg_, kend_);                               \
    for (int k0 = (kbeg_); k0 < (kend_); k0 += 32) {                    \
        _Pragma("unroll")                                               \
        for (int j = 0; j < 4; j++) { int id = tid*4+j; Xs[id>>5][id&31] = rx[j]; } \
        _Pragma("unroll")                                               \
        for (int j = 0; j < 16; j++) { int id = tid + j*128; Ws[id>>6][id&63] = rw[j]; } \
        __syncthreads();                                                \
        if (k0 + 32 < (kend_)) GEMM_LOAD(XP, WP, LDX, k0 + 32, kend_);  \
        _Pragma("unroll")                                               \
        for (int kk = 0; kk < 32; kk++) {                               \
            float a0 = Xs[tm*2][kk], a1 = Xs[tm*2+1][kk];               \
            float4 b = *(const float4*)&Ws[kk][tn*4];                   \
            acc[0][0]=__fmaf_rn(a0,b.x,acc[0][0]); acc[0][1]=__fmaf_rn(a0,b.y,acc[0][1]); \
            acc[0][2]=__fmaf_rn(a0,b.z,acc[0][2]); acc[0][3]=__fmaf_rn(a0,b.w,acc[0][3]); \
            acc[1][0]=__fmaf_rn(a1,b.x,acc[1][0]); acc[1][1]=__fmaf_rn(a1,b.y,acc[1][1]); \
            acc[1][2]=__fmaf_rn(a1,b.z,acc[1][2]); acc[1][3]=__fmaf_rn(a1,b.w,acc[1][3]); \
        }                                                               \
        __syncthreads();                                                \
    }

// plain GEMM: out = relu?(X@W + bias)
__global__ __launch_bounds__(128) void k_gemm(int M, int N, int K,
                                              const float* __restrict__ X,
                                              const float* __restrict__ W,
                                              const float* __restrict__ bias,
                                              float* __restrict__ out, int relu) {
    __shared__ float Xs[16][33];
    __shared__ __align__(16) float Ws[32][64];
    int m0 = blockIdx.x*16, n0 = blockIdx.y*64;
    int tid = threadIdx.x, tn = tid & 15, tm = tid >> 4;
    GEMM_BODY(X, W, K, 0, K);
#pragma unroll
    for (int i = 0; i < 2; i++) {
        int m = m0 + tm*2 + i;
        if (m < M)
#pragma unroll
            for (int j = 0; j < 4; j++) {
                int n = n0 + tn*4 + j;
                float y = acc[i][j];
                if (bias) y = __fadd_rn(y, bias[n]);
                if (relu) y = fmaxf(y, 0.f);
                out[m*N+n] = y;
            }
    }
}

// Fused split-K GEMM: partials + last-block reduce + bias + relu
// (+ optional residual GEMM: out = relu(relu(sum+bias) + resX@resW))
__global__ __launch_bounds__(128) void k_skf(int M, int N, int K, int Kc, int S,
                                             const float* __restrict__ X,
                                             const float* __restrict__ W,
                                             const float* __restrict__ bias,
                                             const float* __restrict__ resX,
                                             const float* __restrict__ resW, int Kres,
                                             float* __restrict__ out) {
    __shared__ float Xs[16][33];
    __shared__ __align__(16) float Ws[32][64];
    __shared__ int sLast;
    int m0 = blockIdx.x*16, n0 = blockIdx.y*64, z = blockIdx.z;
    int kbeg = z * Kc, kend = min(K, kbeg + Kc);
    int tid = threadIdx.x, tn = tid & 15, tm = tid >> 4;
    int MN = M * N;
    {
        GEMM_BODY(X, W, K, kbeg, kend);
        float* dst = g_part + (size_t)z * MN;
#pragma unroll
        for (int i = 0; i < 2; i++) {
            int m = m0 + tm*2 + i;
            if (m < M)
#pragma unroll
                for (int j = 0; j < 4; j++) dst[m*N + n0 + tn*4 + j] = acc[i][j];
        }
    }
    __threadfence();
    int tileId = blockIdx.y * gridDim.x + blockIdx.x;
    if (tid == 0) {
        int old = atomicAdd(&g_ctr[tileId], 1);
        sLast = (old == S - 1) ? 1 : 0;
    }
    __syncthreads();
    if (!sLast) return;
    if (tid == 0) g_ctr[tileId] = 0;          // reset for next launch/replay
    __threadfence();                          // acquire: see other blocks' partials
    float racc[2][4] = {};
    if (resX) {
        GEMM_BODY(resX, resW, Kres, 0, Kres);
#pragma unroll
        for (int i = 0; i < 2; i++)
#pragma unroll
            for (int j = 0; j < 4; j++) racc[i][j] = acc[i][j];
    }
#pragma unroll
    for (int i = 0; i < 2; i++) {
        int m = m0 + tm*2 + i;
        if (m < M)
#pragma unroll
            for (int j = 0; j < 4; j++) {
                int n = n0 + tn*4 + j;
                int i0 = m*N + n;
                float x = g_part[i0];
                for (int z2 = 1; z2 < S; z2++)
                    x = __fadd_rn(x, g_part[(size_t)z2*MN + i0]);
                x = __fadd_rn(x, bias[n]);
                x = fmaxf(x, 0.f);
                if (resX) x = fmaxf(__fadd_rn(x, racc[i][j]), 0.f);
                out[i0] = x;
            }
    }
}

__global__ __launch_bounds__(128) void k_head(const float* __restrict__ hw,
                                              const float* __restrict__ hb,
                                              float* __restrict__ out) {
    __shared__ float red[128];
    int tid = threadIdx.x;
    float acc = 0.f;
    for (int i = tid; i < 512; i += 128)
        acc = __fmaf_rn(g_f4[i], hw[i], acc);
    red[tid] = acc;
    __syncthreads();
    for (int s = 64; s > 0; s >>= 1) {
        if (tid < s) red[tid] = __fadd_rn(red[tid], red[tid+s]);
        __syncthreads();
    }
    if (tid == 0) out[0] = __fadd_rn(red[0], hb[0]);
}

extern "C" void kernel_launch(void* const* d_in, const int* in_sizes, int n_in,
                              void* d_out, int out_size) {
    const float* pos  = (const float*)d_in[0];
    const float* chan = (const float*)d_in[1];
    const float* w[7]; const float* b[7];
    for (int li = 0; li < 7; li++) { w[li] = (const float*)d_in[2+2*li]; b[li] = (const float*)d_in[3+2*li]; }
    const float* p1 = (const float*)d_in[16];
    const float* p2 = (const float*)d_in[17];
    const float* p3 = (const float*)d_in[18];
    const float* p4 = (const float*)d_in[19];
    const float* hw = (const float*)d_in[20];
    const float* hb = (const float*)d_in[21];
    float* out = (float*)d_out;

    void* pv;
    cudaGetSymbolAddress(&pv, g_t);    float* tp  = (float*)pv;
    cudaGetSymbolAddress(&pv, g_xa);   float* xa  = (float*)pv;
    cudaGetSymbolAddress(&pv, g_f1);   float* f1  = (float*)pv;
    cudaGetSymbolAddress(&pv, g_f2);   float* f2  = (float*)pv;
    cudaGetSymbolAddress(&pv, g_f3);   float* f3  = (float*)pv;
    cudaGetSymbolAddress(&pv, g_f4);   float* f4  = (float*)pv;
    cudaGetSymbolAddress(&pv, g_idx1); int* i1 = (int*)pv;
    cudaGetSymbolAddress(&pv, g_cov1); float* c1 = (float*)pv;
    cudaGetSymbolAddress(&pv, g_idx2); int* i2 = (int*)pv;
    cudaGetSymbolAddress(&pv, g_cov2); float* c2 = (float*)pv;
    cudaGetSymbolAddress(&pv, g_idx4); int* i4 = (int*)pv;
    cudaGetSymbolAddress(&pv, g_cov4); float* c4 = (float*)pv;
    cudaGetSymbolAddress(&pv, g_idx6); int* i6 = (int*)pv;
    cudaGetSymbolAddress(&pv, g_cov6); float* c6 = (float*)pv;

    k_prep<<<(NPTS+255)/256, 256>>>(pos, NPTS);
    k_mknn<<<635, 256>>>();

    // L1
    k_tker<<<2435, 128>>>(16, 4, chan, tp, i1, c1);
    k_gemm<<<dim3((2435+15)/16, 1), 128>>>(2435, 64, 180, tp, w[0], b[0], xa, 1);

    // L2 ; f1 = relu(relu(t@W2+b2) + chan@p1)
    k_tker<<<2435, 128>>>(16, 64, xa, tp, i2, c2);
    k_skf<<<dim3((2435+15)/16, 1, 4), 128>>>(2435, 64, 2880, 720, 4,
                                             tp, w[1], b[1], chan, p1, 4, f1);

    // L3 (kNN/cov prefix-reuse of L2)
    k_tker<<<181, 128>>>(16, 64, f1, tp, i2, c2);
    k_skf<<<dim3((181+15)/16, 2, 8), 128>>>(181, 128, 2880, 360, 8,
                                            tp, w[2], b[2], nullptr, nullptr, 0, xa);

    // L4 ; f2 = relu(relu(t@W4+b4) + f1[:181]@p2)
    k_tker<<<181, 128>>>(16, 128, xa, tp, i4, c4);
    k_skf<<<dim3((181+15)/16, 2, 8), 128>>>(181, 128, 5760, 720, 8,
                                            tp, w[3], b[3], f1, p2, 64, f2);

    // L5 (prefix-reuse of L4)
    k_tker<<<13, 128>>>(16, 128, f2, tp, i4, c4);
    k_skf<<<dim3(1, 4, 16), 128>>>(13, 256, 5760, 360, 16,
                                   tp, w[4], b[4], nullptr, nullptr, 0, xa);

    // L6 ; f3 = relu(relu(t@W6+b6) + f2[:13]@p3)
    k_tker<<<13, 128>>>(13, 256, xa, tp, i6, c6);
    k_skf<<<dim3(1, 4, 32), 128>>>(13, 256, 11520, 360, 32,
                                   tp, w[5], b[5], f2, p3, 128, f3);

    // L7 (prefix-reuse of L6)
    k_tker<<<1, 128>>>(13, 256, f3, tp, i6, c6);
    k_skf<<<dim3(1, 8, 32), 128>>>(1, 512, 11520, 360, 32,
                                   tp, w[6], b[6], f3, p4, 256, f4);

    k_head<<<1, 128>>>(hw, hb, out);
}